// round 1
// baseline (speedup 1.0000x reference)
#include <cuda_runtime.h>

#define G 128
#define NT 384
#define NW 12
#define WU 512
#define WCOLS 1536

// ---------------- device scratch (static, no allocation) ----------------
__device__ float g_h[2][WU];
__device__ float g_bufA[16 * WU];
__device__ float g_bufB[16 * WU];
__device__ float g_h1[15 * WU];
__device__ float g_ghp[15 * WCOLS];
__device__ float g_gxc[15 * WCOLS];
__device__ float g_gpart[2 * WCOLS];
__device__ unsigned g_count;
__device__ unsigned g_gen;

__global__ void sg_init() { g_count = 0u; g_gen = 0u; }

// Grid-wide barrier. Valid because grid (128) <= SM count (152) => single wave,
// all CTAs co-resident. Release: per-thread __threadfence before arrive.
// Consumers read cross-CTA data with __ldcg (L2-direct, no stale L1).
__device__ __forceinline__ void grid_sync(unsigned &gen) {
  unsigned next = gen + 1u;
  __threadfence();
  __syncthreads();
  if (threadIdx.x == 0) {
    if (atomicAdd(&g_count, 1u) == G - 1u) {
      atomicExch(&g_count, 0u);
      __threadfence();
      atomicExch(&g_gen, next);
    } else {
      while (*(volatile unsigned *)&g_gen < next) { }
    }
  }
  gen = next;
  __syncthreads();
}

__device__ __forceinline__ float sigmoidf_(float x) {
  return 1.0f / (1.0f + __expf(-x));
}
__device__ __forceinline__ float tanhf_(float x) {
  float ax = fabsf(x);
  float e = __expf(-2.0f * ax);
  float t = (1.0f - e) / (1.0f + e);
  return copysignf(t, x);
}

__global__ void __launch_bounds__(NT, 1) synchron_kernel(
    const float *__restrict__ x,
    const float *__restrict__ k0_1, const float *__restrict__ rk0_1,
    const float *__restrict__ b0_1, const float *__restrict__ kc_1,
    const float *__restrict__ rkc_1, const float *__restrict__ bc_1,
    const float *__restrict__ k0_2, const float *__restrict__ rk0_2,
    const float *__restrict__ b0_2, const float *__restrict__ kc_2,
    const float *__restrict__ rkc_2, const float *__restrict__ bc_2,
    const float *__restrict__ k0_3, const float *__restrict__ rk0_3,
    const float *__restrict__ b0_3, const float *__restrict__ kc_3,
    const float *__restrict__ rkc_3, const float *__restrict__ bc_3,
    float *__restrict__ out)
{
  const float *K0[3]  = {k0_1, k0_2, k0_3};
  const float *RK0[3] = {rk0_1, rk0_2, rk0_3};
  const float *B0[3]  = {b0_1, b0_2, b0_3};
  const float *KC[3]  = {kc_1, kc_2, kc_3};
  const float *RKC[3] = {rkc_1, rkc_2, rkc_3};
  const float *BC[3]  = {bc_1, bc_2, bc_3};
  const float *LIN[3] = {x, g_bufA, g_bufB};
  float *LOUT[3]      = {g_bufA, g_bufB, out};

  __shared__ __align__(16) float sm_w[NW][WU];  // rec columns for this CTA's 4 units
  __shared__ __align__(16) float sm_h[WU];
  __shared__ float sm_x0[WU];
  __shared__ float sm_x1[WU];
  __shared__ float sm_dot[NW];
  __shared__ float sm_k0[NW], sm_bi[NW], sm_br[NW];
  __shared__ float sm_part[NW * 32];

  const int bid  = blockIdx.x;
  const int tid  = threadIdx.x;
  const int warp = tid >> 5;
  const int lane = tid & 31;
  unsigned gen = 0;

  for (int l = 0; l < 3; ++l) {
    const float *lin = LIN[l];
    float *lout = LOUT[l];
    const float *k0  = K0[l];
    const float *rk0 = RK0[l];
    const float *b0  = B0[l];
    const float *kc  = KC[l];
    const float *rkc = RKC[l];
    const float *bc  = BC[l];

    // ---------------- per-layer setup ----------------
    for (int i = tid; i < WU; i += NT) {
      sm_x0[i] = __ldcg(lin + i * 16);      // channel 0
      sm_x1[i] = __ldcg(lin + i * 16 + 1);  // channel 1
    }
    // cache rec[:, {z,r,n} cols of units 4*bid..4*bid+3] transposed into SMEM
    for (int idx = tid; idx < NW * WU; idx += NT) {
      int lc  = idx / WU;
      int row = idx - lc * WU;
      int lu = lc / 3, gate = lc - lu * 3;
      int col = gate * WU + bid * 4 + lu;
      sm_w[lc][row] = __ldg(rk0 + row * WCOLS + col);
    }
    if (tid < NW) {
      int lu = tid / 3, gate = tid - lu * 3;
      int col = gate * WU + bid * 4 + lu;
      sm_k0[tid] = __ldg(k0 + col);
      sm_bi[tid] = __ldg(b0 + col);
      sm_br[tid] = __ldg(b0 + WCOLS + col);
    }
    for (int i = bid * NT + tid; i < WU; i += G * NT) g_h[0][i] = 0.0f;
    __syncthreads();

    // ---------------- phase A: gxc[i][col] = x1 . kc[i][:,col] + b_i ----------------
    {
      int wid = bid * NW + warp;
      if (wid < 15 * 48) {
        int ci = wid / 48, cb = wid - ci * 48;
        int col = cb * 32 + lane;
        const float *wp = kc + ci * (WU * WCOLS) + col;
        float a0 = 0, a1 = 0, a2 = 0, a3 = 0, a4 = 0, a5 = 0, a6 = 0, a7 = 0;
        for (int r = 0; r < WU; r += 8) {
          a0 = fmaf(sm_x1[r + 0], __ldg(wp + (r + 0) * WCOLS), a0);
          a1 = fmaf(sm_x1[r + 1], __ldg(wp + (r + 1) * WCOLS), a1);
          a2 = fmaf(sm_x1[r + 2], __ldg(wp + (r + 2) * WCOLS), a2);
          a3 = fmaf(sm_x1[r + 3], __ldg(wp + (r + 3) * WCOLS), a3);
          a4 = fmaf(sm_x1[r + 4], __ldg(wp + (r + 4) * WCOLS), a4);
          a5 = fmaf(sm_x1[r + 5], __ldg(wp + (r + 5) * WCOLS), a5);
          a6 = fmaf(sm_x1[r + 6], __ldg(wp + (r + 6) * WCOLS), a6);
          a7 = fmaf(sm_x1[r + 7], __ldg(wp + (r + 7) * WCOLS), a7);
        }
        float s = ((a0 + a1) + (a2 + a3)) + ((a4 + a5) + (a6 + a7));
        g_gxc[ci * WCOLS + col] = s + __ldg(bc + ci * 3072 + col);
      }
    }
    grid_sync(gen);

    // ---------------- h1 pointwise (chain step 1, h=0) ----------------
    {
      int e = bid * NT + tid;
      if (e < 15 * WU) {
        int ci = e >> 9, u = e & (WU - 1);
        float gz = __ldcg(g_gxc + ci * WCOLS + u);
        float gr = __ldcg(g_gxc + ci * WCOLS + WU + u);
        float gn = __ldcg(g_gxc + ci * WCOLS + 2 * WU + u);
        float brz = __ldg(bc + ci * 3072 + WCOLS + u);
        float brr = __ldg(bc + ci * 3072 + WCOLS + WU + u);
        float brn = __ldg(bc + ci * 3072 + WCOLS + 2 * WU + u);
        float z = sigmoidf_(gz + brz);
        float r = sigmoidf_(gr + brr);
        float hh = tanhf_(gn + r * brn);
        g_h1[e] = (1.0f - z) * hh;
      }
    }
    grid_sync(gen);

    // ---------------- phase B: ghp[i][col] = h1[i] . rkc[i][:,col] + b_r ----------------
    {
      int wid = bid * NW + warp;
      if (wid < 15 * 48) {
        int ci = wid / 48, cb = wid - ci * 48;
        int col = cb * 32 + lane;
        const float *wp = rkc + ci * (WU * WCOLS) + col;
        const float *hp = g_h1 + ci * WU;
        float a0 = 0, a1 = 0, a2 = 0, a3 = 0, a4 = 0, a5 = 0, a6 = 0, a7 = 0;
        for (int r = 0; r < WU; r += 8) {
          a0 = fmaf(__ldcg(hp + r + 0), __ldg(wp + (r + 0) * WCOLS), a0);
          a1 = fmaf(__ldcg(hp + r + 1), __ldg(wp + (r + 1) * WCOLS), a1);
          a2 = fmaf(__ldcg(hp + r + 2), __ldg(wp + (r + 2) * WCOLS), a2);
          a3 = fmaf(__ldcg(hp + r + 3), __ldg(wp + (r + 3) * WCOLS), a3);
          a4 = fmaf(__ldcg(hp + r + 4), __ldg(wp + (r + 4) * WCOLS), a4);
          a5 = fmaf(__ldcg(hp + r + 5), __ldg(wp + (r + 5) * WCOLS), a5);
          a6 = fmaf(__ldcg(hp + r + 6), __ldg(wp + (r + 6) * WCOLS), a6);
          a7 = fmaf(__ldcg(hp + r + 7), __ldg(wp + (r + 7) * WCOLS), a7);
        }
        float s = ((a0 + a1) + (a2 + a3)) + ((a4 + a5) + (a6 + a7));
        g_ghp[ci * WCOLS + col] = s + __ldg(bc + ci * 3072 + WCOLS + col);
      }
    }
    grid_sync(gen);

    // ---------------- GRU0: 512 sequential steps ----------------
    for (int t = 0; t < WU; ++t) {
      int cur = t & 1;
      for (int i = tid; i < WU; i += NT) sm_h[i] = __ldcg(&g_h[cur][i]);
      __syncthreads();

      float acc = 0.0f;
      {
        const float4 *h4 = (const float4 *)sm_h;
        const float4 *w4 = (const float4 *)sm_w[warp];
#pragma unroll
        for (int k = 0; k < 4; ++k) {
          float4 hv = h4[lane + 32 * k];
          float4 wv = w4[lane + 32 * k];
          acc += hv.x * wv.x + hv.y * wv.y;
          acc += hv.z * wv.z + hv.w * wv.w;
        }
      }
#pragma unroll
      for (int o = 16; o; o >>= 1) acc += __shfl_xor_sync(0xffffffffu, acc, o);
      if (lane == 0) sm_dot[warp] = acc;
      __syncthreads();

      if (tid < 4) {
        float dz = sm_dot[tid * 3 + 0] + sm_br[tid * 3 + 0];
        float dr = sm_dot[tid * 3 + 1] + sm_br[tid * 3 + 1];
        float dn = sm_dot[tid * 3 + 2] + sm_br[tid * 3 + 2];
        float xt = sm_x0[t];
        float gz = fmaf(xt, sm_k0[tid * 3 + 0], sm_bi[tid * 3 + 0]);
        float gr = fmaf(xt, sm_k0[tid * 3 + 1], sm_bi[tid * 3 + 1]);
        float gn = fmaf(xt, sm_k0[tid * 3 + 2], sm_bi[tid * 3 + 2]);
        float z = sigmoidf_(gz + dz);
        float r = sigmoidf_(gr + dr);
        float hh = tanhf_(gn + r * dn);
        int u = bid * 4 + tid;
        float hnew = z * sm_h[u] + (1.0f - z) * hh;
        g_h[cur ^ 1][u] = hnew;
        if (t == WU - 1) lout[u] = hnew;  // y_all[0] = y0
      }
      grid_sync(gen);
    }

    // ---------------- serial chain: 15 steps ----------------
    for (int ci = 0; ci < 15; ++ci) {
      const float *yprev = lout + ci * WU;
      // pass1: gpart[half][col] = partial of y_prev . kc[ci][:,col]
      if (bid < 96) {
        int cb = bid >> 1, half = bid & 1;
        int col = cb * 32 + lane;
        const float *wp = kc + ci * (WU * WCOLS) + col;
        float acc = 0.0f;
        for (int r0 = warp; r0 < 256; r0 += NW) {
          int r = half * 256 + r0;
          acc = fmaf(__ldcg(yprev + r), __ldg(wp + r * WCOLS), acc);
        }
        sm_part[warp * 32 + lane] = acc;
        __syncthreads();
        if (warp == 0) {
          float s = 0.0f;
#pragma unroll
          for (int w2 = 0; w2 < NW; ++w2) s += sm_part[w2 * 32 + lane];
          g_gpart[half * WCOLS + col] = s;
        }
      }
      grid_sync(gen);
      // pass2: gates + y
      {
        int u = bid * NT + tid;
        if (u < WU) {
          float gxz = __ldcg(g_gpart + u) + __ldcg(g_gpart + WCOLS + u) +
                      __ldg(bc + ci * 3072 + u);
          float gxr = __ldcg(g_gpart + WU + u) + __ldcg(g_gpart + WCOLS + WU + u) +
                      __ldg(bc + ci * 3072 + WU + u);
          float gxh = __ldcg(g_gpart + 2 * WU + u) + __ldcg(g_gpart + WCOLS + 2 * WU + u) +
                      __ldg(bc + ci * 3072 + 2 * WU + u);
          float ghz = __ldcg(g_ghp + ci * WCOLS + u);
          float ghr = __ldcg(g_ghp + ci * WCOLS + WU + u);
          float ghn = __ldcg(g_ghp + ci * WCOLS + 2 * WU + u);
          float h1v = __ldcg(g_h1 + ci * WU + u);
          float z = sigmoidf_(gxz + ghz);
          float r = sigmoidf_(gxr + ghr);
          float hh = tanhf_(gxh + r * ghn);
          lout[(ci + 1) * WU + u] = z * h1v + (1.0f - z) * hh;
        }
      }
      grid_sync(gen);
    }
  }
}

extern "C" void kernel_launch(void *const *d_in, const int *in_sizes, int n_in,
                              void *d_out, int out_size) {
  (void)in_sizes; (void)n_in; (void)out_size;
  const float *x     = (const float *)d_in[0];
  const float *k0_1  = (const float *)d_in[1];
  const float *rk0_1 = (const float *)d_in[2];
  const float *b0_1  = (const float *)d_in[3];
  const float *kc_1  = (const float *)d_in[4];
  const float *rkc_1 = (const float *)d_in[5];
  const float *bc_1  = (const float *)d_in[6];
  const float *k0_2  = (const float *)d_in[7];
  const float *rk0_2 = (const float *)d_in[8];
  const float *b0_2  = (const float *)d_in[9];
  const float *kc_2  = (const float *)d_in[10];
  const float *rkc_2 = (const float *)d_in[11];
  const float *bc_2  = (const float *)d_in[12];
  const float *k0_3  = (const float *)d_in[13];
  const float *rk0_3 = (const float *)d_in[14];
  const float *b0_3  = (const float *)d_in[15];
  const float *kc_3  = (const float *)d_in[16];
  const float *rkc_3 = (const float *)d_in[17];
  const float *bc_3  = (const float *)d_in[18];

  sg_init<<<1, 1>>>();
  synchron_kernel<<<G, NT>>>(x, k0_1, rk0_1, b0_1, kc_1, rkc_1, bc_1,
                             k0_2, rk0_2, b0_2, kc_2, rkc_2, bc_2,
                             k0_3, rk0_3, b0_3, kc_3, rkc_3, bc_3,
                             (float *)d_out);
}

// round 3
// speedup vs baseline: 1.2913x; 1.2913x over previous
#include <cuda_runtime.h>
#include <cstdint>

#define NT 384
#define NW 12
#define WU 512
#define WCOLS 1536
#define GP 128   // phases grid
#define GC 96    // chain grid
#define CL 16    // GRU0 cluster size
#define GT 512   // GRU0 threads per CTA

typedef unsigned long long u64;

// ---------------- device scratch (static, no allocation) ----------------
__device__ float g_bufA[16 * WU];
__device__ float g_bufB[16 * WU];
__device__ float g_h1[15 * WU];
__device__ float g_ghp[15 * WCOLS];
__device__ float g_gxc[15 * WCOLS];
__device__ float g_gpart[2 * WCOLS];
__device__ unsigned g_count;
__device__ unsigned g_gen;

// Grid-wide barrier among nct co-resident CTAs. Generation continues
// monotonically across kernel launches (wrap-safe signed compare).
__device__ __forceinline__ void grid_sync(unsigned &gen, unsigned nct) {
  unsigned next = gen + 1u;
  __threadfence();
  __syncthreads();
  if (threadIdx.x == 0) {
    if (atomicAdd(&g_count, 1u) == nct - 1u) {
      atomicExch(&g_count, 0u);
      __threadfence();
      atomicExch(&g_gen, next);
    } else {
      while ((int)(*(volatile unsigned *)&g_gen - next) < 0) { }
    }
  }
  gen = next;
  __syncthreads();
}

__device__ __forceinline__ float sigmoidf_(float x) {
  return 1.0f / (1.0f + __expf(-x));
}
__device__ __forceinline__ float tanhf_(float x) {
  float ax = fabsf(x);
  float e = __expf(-2.0f * ax);
  float t = (1.0f - e) / (1.0f + e);
  return copysignf(t, x);
}
__device__ __forceinline__ float sigf_fast(float x) {
  return __fdividef(1.0f, 1.0f + __expf(-x));
}
__device__ __forceinline__ float tanhf_fast(float x) {
  float ax = fabsf(x);
  float e = __expf(-2.0f * ax);
  float t = __fdividef(1.0f - e, 1.0f + e);
  return copysignf(t, x);
}

// ---------------- Blackwell helpers ----------------
__device__ __forceinline__ void ffma2(u64 &acc, u64 a, u64 b) {
  asm("fma.rn.f32x2 %0, %1, %2, %0;" : "+l"(acc) : "l"(a), "l"(b));
}
__device__ __forceinline__ float hsum2(u64 v) {
  float lo, hi;
  asm("mov.b64 {%0,%1}, %2;" : "=f"(lo), "=f"(hi) : "l"(v));
  return lo + hi;
}
// Paired half-warp reduction: lo lanes (0-15) return full-warp sum of d0,
// hi lanes (16-31) return full-warp sum of d1. 5 shuffle levels total.
__device__ __forceinline__ float pair_reduce(float d0, float d1, bool hi) {
  float own = hi ? d1 : d0;
  float oth = hi ? d0 : d1;
  float s = own + __shfl_xor_sync(0xffffffffu, oth, 16);
#pragma unroll
  for (int o = 8; o; o >>= 1) s += __shfl_xor_sync(0xffffffffu, s, o);
  return s;
}
__device__ __forceinline__ void st_cluster(uint32_t laddr, unsigned rank, float v) {
  uint32_t raddr;
  asm volatile("mapa.shared::cluster.u32 %0, %1, %2;" : "=r"(raddr) : "r"(laddr), "r"(rank));
  asm volatile("st.shared::cluster.f32 [%0], %1;" :: "r"(raddr), "f"(v) : "memory");
}
__device__ __forceinline__ void cluster_sync_() {
  asm volatile("barrier.cluster.arrive.aligned;" ::: "memory");
  asm volatile("barrier.cluster.wait.aligned;" ::: "memory");
}

// =====================================================================
// Phases kernel (full grid, 128 CTAs): gxc -> h1 -> ghp for all 15 chain GRUs
// =====================================================================
__global__ void __launch_bounds__(NT, 1) phases_kernel(
    const float *__restrict__ lin, const float *__restrict__ kc,
    const float *__restrict__ rkc, const float *__restrict__ bc)
{
  __shared__ float sm_x1[WU];
  const int bid = blockIdx.x, tid = threadIdx.x;
  const int warp = tid >> 5, lane = tid & 31;
  unsigned gen = *(volatile unsigned *)&g_gen;

  for (int i = tid; i < WU; i += NT) sm_x1[i] = __ldcg(lin + i * 16 + 1);
  __syncthreads();

  // phase A: gxc[ci][col] = x1 . kc[ci][:,col] + b_i
  {
    int wid = bid * NW + warp;
    if (wid < 15 * 48) {
      int ci = wid / 48, cb = wid - ci * 48;
      int col = cb * 32 + lane;
      const float *wp = kc + (size_t)ci * (WU * WCOLS) + col;
      float a0 = 0, a1 = 0, a2 = 0, a3 = 0, a4 = 0, a5 = 0, a6 = 0, a7 = 0;
      for (int r = 0; r < WU; r += 8) {
        a0 = fmaf(sm_x1[r + 0], __ldg(wp + (r + 0) * WCOLS), a0);
        a1 = fmaf(sm_x1[r + 1], __ldg(wp + (r + 1) * WCOLS), a1);
        a2 = fmaf(sm_x1[r + 2], __ldg(wp + (r + 2) * WCOLS), a2);
        a3 = fmaf(sm_x1[r + 3], __ldg(wp + (r + 3) * WCOLS), a3);
        a4 = fmaf(sm_x1[r + 4], __ldg(wp + (r + 4) * WCOLS), a4);
        a5 = fmaf(sm_x1[r + 5], __ldg(wp + (r + 5) * WCOLS), a5);
        a6 = fmaf(sm_x1[r + 6], __ldg(wp + (r + 6) * WCOLS), a6);
        a7 = fmaf(sm_x1[r + 7], __ldg(wp + (r + 7) * WCOLS), a7);
      }
      float s = ((a0 + a1) + (a2 + a3)) + ((a4 + a5) + (a6 + a7));
      g_gxc[ci * WCOLS + col] = s + __ldg(bc + ci * 3072 + col);
    }
  }
  grid_sync(gen, GP);

  // h1 pointwise (chain step 1, h=0)
  {
    int e = bid * NT + tid;
    if (e < 15 * WU) {
      int ci = e >> 9, u = e & (WU - 1);
      float gz = __ldcg(g_gxc + ci * WCOLS + u);
      float gr = __ldcg(g_gxc + ci * WCOLS + WU + u);
      float gn = __ldcg(g_gxc + ci * WCOLS + 2 * WU + u);
      float brz = __ldg(bc + ci * 3072 + WCOLS + u);
      float brr = __ldg(bc + ci * 3072 + WCOLS + WU + u);
      float brn = __ldg(bc + ci * 3072 + WCOLS + 2 * WU + u);
      float z = sigmoidf_(gz + brz);
      float r = sigmoidf_(gr + brr);
      float hh = tanhf_(gn + r * brn);
      g_h1[e] = (1.0f - z) * hh;
    }
  }
  grid_sync(gen, GP);

  // phase B: ghp[ci][col] = h1[ci] . rkc[ci][:,col] + b_r
  {
    int wid = bid * NW + warp;
    if (wid < 15 * 48) {
      int ci = wid / 48, cb = wid - ci * 48;
      int col = cb * 32 + lane;
      const float *wp = rkc + (size_t)ci * (WU * WCOLS) + col;
      const float *hp = g_h1 + ci * WU;
      float a0 = 0, a1 = 0, a2 = 0, a3 = 0, a4 = 0, a5 = 0, a6 = 0, a7 = 0;
      for (int r = 0; r < WU; r += 8) {
        a0 = fmaf(__ldcg(hp + r + 0), __ldg(wp + (r + 0) * WCOLS), a0);
        a1 = fmaf(__ldcg(hp + r + 1), __ldg(wp + (r + 1) * WCOLS), a1);
        a2 = fmaf(__ldcg(hp + r + 2), __ldg(wp + (r + 2) * WCOLS), a2);
        a3 = fmaf(__ldcg(hp + r + 3), __ldg(wp + (r + 3) * WCOLS), a3);
        a4 = fmaf(__ldcg(hp + r + 4), __ldg(wp + (r + 4) * WCOLS), a4);
        a5 = fmaf(__ldcg(hp + r + 5), __ldg(wp + (r + 5) * WCOLS), a5);
        a6 = fmaf(__ldcg(hp + r + 6), __ldg(wp + (r + 6) * WCOLS), a6);
        a7 = fmaf(__ldcg(hp + r + 7), __ldg(wp + (r + 7) * WCOLS), a7);
      }
      float s = ((a0 + a1) + (a2 + a3)) + ((a4 + a5) + (a6 + a7));
      g_ghp[ci * WCOLS + col] = s + __ldg(bc + ci * 3072 + WCOLS + col);
    }
  }
}

// =====================================================================
// GRU0 kernel: 16-CTA cluster, weights in SMEM, DSMEM h-broadcast
// =====================================================================
#define GRU0_SMEM ((96 * WU + 2 * WU + WU) * 4)

__global__ void __launch_bounds__(GT, 1) gru0_kernel(
    const float *__restrict__ lin, const float *__restrict__ k0,
    const float *__restrict__ rk0, const float *__restrict__ b0,
    float *__restrict__ lout)
{
  extern __shared__ float sm[];
  float *sw  = sm;               // [32 units][3 gates][512] fp32 = 192KB
  float *sh  = sm + 96 * WU;     // [2][512] double-buffered full h
  float *sx0 = sh + 2 * WU;      // [512]

  unsigned rank;
  asm("mov.u32 %0, %%cluster_ctarank;" : "=r"(rank));
  const int tid = threadIdx.x, warp = tid >> 5, lane = tid & 31;
  const int base = (int)rank * 32;

  for (int i = tid; i < WU; i += GT) sx0[i] = __ldg(lin + 16 * i);
  for (int i = tid; i < 2 * WU; i += GT) sh[i] = 0.0f;
  // load this CTA's 96 rec columns, transposed to [u][g][k]
  for (int idx = tid; idx < 96 * WU; idx += GT) {
    int k = idx / 96, cl2 = idx - k * 96;
    int g = cl2 >> 5, u = cl2 & 31;
    sw[(u * 3 + g) * WU + k] = __ldg(rk0 + (size_t)k * WCOLS + g * WU + base + u);
  }

  // per-lane unit: lanes 0-15 -> unit 2*warp, lanes 16-31 -> unit 2*warp+1
  const bool hi = (lane >= 16);
  const int gu = base + 2 * warp + (hi ? 1 : 0);
  const float kz  = __ldg(k0 + gu);
  const float kr  = __ldg(k0 + WU + gu);
  const float kn  = __ldg(k0 + 2 * WU + gu);
  const float cbz = __ldg(b0 + gu) + __ldg(b0 + WCOLS + gu);
  const float cbr = __ldg(b0 + WU + gu) + __ldg(b0 + WCOLS + WU + gu);
  const float bin = __ldg(b0 + 2 * WU + gu);
  const float brn = __ldg(b0 + WCOLS + 2 * WU + gu);

  const float *w0 = sw + (size_t)(2 * warp) * 3 * WU;
  const float *w1 = w0 + 3 * WU;
  const uint32_t sh_u32 = (uint32_t)__cvta_generic_to_shared(sh);
  const unsigned trank = lane & 15;

  __syncthreads();
  cluster_sync_();

  int cur = 0;
  for (int t = 0; t < WU; ++t) {
    const float *hb = sh + cur * WU;
    u64 az0 = 0, ar0 = 0, an0 = 0, az1 = 0, ar1 = 0, an1 = 0;
#pragma unroll
    for (int c = 0; c < 4; ++c) {
      const int off = c * 128 + lane * 4;
      ulonglong2 hv = *(const ulonglong2 *)(hb + off);
      {
        ulonglong2 wz = *(const ulonglong2 *)(w0 + off);
        ulonglong2 wr = *(const ulonglong2 *)(w0 + WU + off);
        ulonglong2 wn = *(const ulonglong2 *)(w0 + 2 * WU + off);
        ffma2(az0, hv.x, wz.x); ffma2(az0, hv.y, wz.y);
        ffma2(ar0, hv.x, wr.x); ffma2(ar0, hv.y, wr.y);
        ffma2(an0, hv.x, wn.x); ffma2(an0, hv.y, wn.y);
      }
      {
        ulonglong2 wz = *(const ulonglong2 *)(w1 + off);
        ulonglong2 wr = *(const ulonglong2 *)(w1 + WU + off);
        ulonglong2 wn = *(const ulonglong2 *)(w1 + 2 * WU + off);
        ffma2(az1, hv.x, wz.x); ffma2(az1, hv.y, wz.y);
        ffma2(ar1, hv.x, wr.x); ffma2(ar1, hv.y, wr.y);
        ffma2(an1, hv.x, wn.x); ffma2(an1, hv.y, wn.y);
      }
    }
    float dz = pair_reduce(hsum2(az0), hsum2(az1), hi);
    float dr = pair_reduce(hsum2(ar0), hsum2(ar1), hi);
    float dn = pair_reduce(hsum2(an0), hsum2(an1), hi);

    float xt = sx0[t];
    float z  = sigf_fast(fmaf(xt, kz, cbz) + dz);
    float r  = sigf_fast(fmaf(xt, kr, cbr) + dr);
    float hh = tanhf_fast(fmaf(xt, kn, bin) + r * (dn + brn));
    float hold = hb[gu];
    float hnew = hh + z * (hold - hh);

    if (t < WU - 1) {
      uint32_t laddr = sh_u32 + ((unsigned)((cur ^ 1) * WU + gu) << 2);
      st_cluster(laddr, trank, hnew);   // broadcast to all 16 CTAs (incl. self)
      cluster_sync_();
    } else {
      if ((lane & 15) == 0) lout[gu] = hnew;  // y0
    }
    cur ^= 1;
  }
}

// =====================================================================
// Chain kernel (96 CTAs persistent): 15 serial 2-step GRUs
// =====================================================================
__global__ void __launch_bounds__(NT, 1) chain_kernel(
    float *__restrict__ lout, const float *__restrict__ kc,
    const float *__restrict__ bc)
{
  __shared__ float sm_part[NW * 32];
  const int bid = blockIdx.x, tid = threadIdx.x;
  const int warp = tid >> 5, lane = tid & 31;
  unsigned gen = *(volatile unsigned *)&g_gen;

  for (int ci = 0; ci < 15; ++ci) {
    const float *yprev = lout + ci * WU;
    // pass1: gpart[half][col] = partial of y_prev . kc[ci][:,col]
    {
      int cb = bid >> 1, half = bid & 1;
      int col = cb * 32 + lane;
      const float *wp = kc + (size_t)ci * (WU * WCOLS) + col;
      float acc = 0.0f;
      for (int r0 = warp; r0 < 256; r0 += NW) {
        int r = half * 256 + r0;
        acc = fmaf(__ldcg(yprev + r), __ldg(wp + r * WCOLS), acc);
      }
      sm_part[warp * 32 + lane] = acc;
      __syncthreads();
      if (warp == 0) {
        float s = 0.0f;
#pragma unroll
        for (int w2 = 0; w2 < NW; ++w2) s += sm_part[w2 * 32 + lane];
        g_gpart[half * WCOLS + col] = s;
      }
    }
    grid_sync(gen, GC);
    // pass2: gates + y
    {
      int u = bid * NT + tid;
      if (u < WU) {
        float gxz = __ldcg(g_gpart + u) + __ldcg(g_gpart + WCOLS + u) +
                    __ldg(bc + ci * 3072 + u);
        float gxr = __ldcg(g_gpart + WU + u) + __ldcg(g_gpart + WCOLS + WU + u) +
                    __ldg(bc + ci * 3072 + WU + u);
        float gxh = __ldcg(g_gpart + 2 * WU + u) + __ldcg(g_gpart + WCOLS + 2 * WU + u) +
                    __ldg(bc + ci * 3072 + 2 * WU + u);
        float ghz = __ldcg(g_ghp + ci * WCOLS + u);
        float ghr = __ldcg(g_ghp + ci * WCOLS + WU + u);
        float ghn = __ldcg(g_ghp + ci * WCOLS + 2 * WU + u);
        float h1v = __ldcg(g_h1 + ci * WU + u);
        float z = sigmoidf_(gxz + ghz);
        float r = sigmoidf_(gxr + ghr);
        float hh = tanhf_(gxh + r * ghn);
        lout[(ci + 1) * WU + u] = z * h1v + (1.0f - z) * hh;
      }
    }
    grid_sync(gen, GC);
  }
}

// =====================================================================
// Host launcher
// =====================================================================
extern "C" void kernel_launch(void *const *d_in, const int *in_sizes, int n_in,
                              void *d_out, int out_size) {
  (void)in_sizes; (void)n_in; (void)out_size;
  const float *x = (const float *)d_in[0];
  const float *K0[3]  = {(const float *)d_in[1],  (const float *)d_in[7],  (const float *)d_in[13]};
  const float *RK0[3] = {(const float *)d_in[2],  (const float *)d_in[8],  (const float *)d_in[14]};
  const float *B0[3]  = {(const float *)d_in[3],  (const float *)d_in[9],  (const float *)d_in[15]};
  const float *KC[3]  = {(const float *)d_in[4],  (const float *)d_in[10], (const float *)d_in[16]};
  const float *RKC[3] = {(const float *)d_in[5],  (const float *)d_in[11], (const float *)d_in[17]};
  const float *BC[3]  = {(const float *)d_in[6],  (const float *)d_in[12], (const float *)d_in[18]};

  float *pA = nullptr, *pB = nullptr;
  cudaGetSymbolAddress((void **)&pA, g_bufA);
  cudaGetSymbolAddress((void **)&pB, g_bufB);

  cudaFuncSetAttribute(gru0_kernel, cudaFuncAttributeMaxDynamicSharedMemorySize, GRU0_SMEM);
  cudaFuncSetAttribute(gru0_kernel, cudaFuncAttributeNonPortableClusterSizeAllowed, 1);

  const float *LIN[3] = {x, pA, pB};
  float *LOUT[3] = {pA, pB, (float *)d_out};

  for (int l = 0; l < 3; ++l) {
    phases_kernel<<<GP, NT>>>(LIN[l], KC[l], RKC[l], BC[l]);

    cudaLaunchConfig_t cfg = {};
    cfg.gridDim = dim3(CL, 1, 1);
    cfg.blockDim = dim3(GT, 1, 1);
    cfg.dynamicSmemBytes = GRU0_SMEM;
    cfg.stream = 0;
    cudaLaunchAttribute attrs[1];
    attrs[0].id = cudaLaunchAttributeClusterDimension;
    attrs[0].val.clusterDim = {CL, 1, 1};
    cfg.attrs = attrs;
    cfg.numAttrs = 1;
    cudaLaunchKernelEx(&cfg, gru0_kernel, LIN[l], K0[l], RK0[l], B0[l], LOUT[l]);

    chain_kernel<<<GC, NT>>>(LOUT[l], KC[l], BC[l]);
  }
}

// round 4
// speedup vs baseline: 1.6908x; 1.3094x over previous
#include <cuda_runtime.h>
#include <cstdint>

#define NT 384
#define NW 12
#define WU 512
#define WCOLS 1536
#define GP 128   // phases grid
#define GC 96    // chain grid
#define CL 16    // GRU0 cluster size
#define GT 512   // GRU0 threads per CTA

typedef unsigned long long u64;

// ---------------- device scratch (static, no allocation) ----------------
__device__ float g_bufA[16 * WU];
__device__ float g_bufB[16 * WU];
__device__ float g_h1[15 * WU];
__device__ float g_ghp[15 * WCOLS];
__device__ float g_gxc[15 * WCOLS];
__device__ float g_gpart[2 * WCOLS];
__device__ unsigned g_count;
__device__ unsigned g_gen;

// Grid-wide barrier among nct co-resident CTAs. Generation continues
// monotonically across kernel launches (wrap-safe signed compare).
__device__ __forceinline__ void grid_sync(unsigned &gen, unsigned nct) {
  unsigned next = gen + 1u;
  __threadfence();
  __syncthreads();
  if (threadIdx.x == 0) {
    if (atomicAdd(&g_count, 1u) == nct - 1u) {
      atomicExch(&g_count, 0u);
      __threadfence();
      atomicExch(&g_gen, next);
    } else {
      while ((int)(*(volatile unsigned *)&g_gen - next) < 0) { }
    }
  }
  gen = next;
  __syncthreads();
}

__device__ __forceinline__ float sigmoidf_(float x) {
  return 1.0f / (1.0f + __expf(-x));
}
__device__ __forceinline__ float tanhf_(float x) {
  float ax = fabsf(x);
  float e = __expf(-2.0f * ax);
  float t = (1.0f - e) / (1.0f + e);
  return copysignf(t, x);
}
__device__ __forceinline__ float sigf_fast(float x) {
  return __fdividef(1.0f, 1.0f + __expf(-x));
}
__device__ __forceinline__ float tanhf_fast(float x) {
  float ax = fabsf(x);
  float e = __expf(-2.0f * ax);
  float t = __fdividef(1.0f - e, 1.0f + e);
  return copysignf(t, x);
}

// ---------------- Blackwell helpers ----------------
__device__ __forceinline__ void ffma2(u64 &acc, u64 a, u64 b) {
  asm("fma.rn.f32x2 %0, %1, %2, %0;" : "+l"(acc) : "l"(a), "l"(b));
}
__device__ __forceinline__ float hsum2(u64 v) {
  float lo, hi;
  asm("mov.b64 {%0,%1}, %2;" : "=f"(lo), "=f"(hi) : "l"(v));
  return lo + hi;
}
// Paired half-warp reduction: lo lanes (0-15) return full-warp sum of d0,
// hi lanes (16-31) return full-warp sum of d1. 5 shuffle levels total.
__device__ __forceinline__ float pair_reduce(float d0, float d1, bool hi) {
  float own = hi ? d1 : d0;
  float oth = hi ? d0 : d1;
  float s = own + __shfl_xor_sync(0xffffffffu, oth, 16);
#pragma unroll
  for (int o = 8; o; o >>= 1) s += __shfl_xor_sync(0xffffffffu, s, o);
  return s;
}
__device__ __forceinline__ void st_cluster(uint32_t laddr, unsigned rank, float v) {
  uint32_t raddr;
  asm volatile("mapa.shared::cluster.u32 %0, %1, %2;" : "=r"(raddr) : "r"(laddr), "r"(rank));
  asm volatile("st.shared::cluster.f32 [%0], %1;" :: "r"(raddr), "f"(v) : "memory");
}
__device__ __forceinline__ void cluster_sync_() {
  asm volatile("barrier.cluster.arrive.aligned;" ::: "memory");
  asm volatile("barrier.cluster.wait.aligned;" ::: "memory");
}

// =====================================================================
// Phases kernel (full grid, 128 CTAs): gxc -> h1 -> ghp for all 15 chain GRUs
// =====================================================================
__global__ void __launch_bounds__(NT, 1) phases_kernel(
    const float *__restrict__ lin, const float *__restrict__ kc,
    const float *__restrict__ rkc, const float *__restrict__ bc)
{
  __shared__ float sm_x1[WU];
  const int bid = blockIdx.x, tid = threadIdx.x;
  const int warp = tid >> 5, lane = tid & 31;
  unsigned gen = *(volatile unsigned *)&g_gen;

  for (int i = tid; i < WU; i += NT) sm_x1[i] = __ldcg(lin + i * 16 + 1);
  __syncthreads();

  // phase A: gxc[ci][col] = x1 . kc[ci][:,col] + b_i
  {
    int wid = bid * NW + warp;
    if (wid < 15 * 48) {
      int ci = wid / 48, cb = wid - ci * 48;
      int col = cb * 32 + lane;
      const float *wp = kc + (size_t)ci * (WU * WCOLS) + col;
      float a[16];
#pragma unroll
      for (int j = 0; j < 16; ++j) a[j] = 0.0f;
      for (int r = 0; r < WU; r += 16) {
#pragma unroll
        for (int j = 0; j < 16; ++j)
          a[j] = fmaf(sm_x1[r + j], __ldg(wp + (size_t)(r + j) * WCOLS), a[j]);
      }
      float s = 0.0f;
#pragma unroll
      for (int j = 0; j < 16; ++j) s += a[j];
      g_gxc[ci * WCOLS + col] = s + __ldg(bc + ci * 3072 + col);
    }
  }
  grid_sync(gen, GP);

  // h1 pointwise (chain step 1, h=0)
  {
    int e = bid * NT + tid;
    if (e < 15 * WU) {
      int ci = e >> 9, u = e & (WU - 1);
      float gz = __ldcg(g_gxc + ci * WCOLS + u);
      float gr = __ldcg(g_gxc + ci * WCOLS + WU + u);
      float gn = __ldcg(g_gxc + ci * WCOLS + 2 * WU + u);
      float brz = __ldg(bc + ci * 3072 + WCOLS + u);
      float brr = __ldg(bc + ci * 3072 + WCOLS + WU + u);
      float brn = __ldg(bc + ci * 3072 + WCOLS + 2 * WU + u);
      float z = sigmoidf_(gz + brz);
      float r = sigmoidf_(gr + brr);
      float hh = tanhf_(gn + r * brn);
      g_h1[e] = (1.0f - z) * hh;
    }
  }
  grid_sync(gen, GP);

  // phase B: ghp[ci][col] = h1[ci] . rkc[ci][:,col] + b_r
  {
    int wid = bid * NW + warp;
    if (wid < 15 * 48) {
      int ci = wid / 48, cb = wid - ci * 48;
      int col = cb * 32 + lane;
      const float *wp = rkc + (size_t)ci * (WU * WCOLS) + col;
      const float *hp = g_h1 + ci * WU;
      float a[16];
#pragma unroll
      for (int j = 0; j < 16; ++j) a[j] = 0.0f;
      for (int r = 0; r < WU; r += 16) {
#pragma unroll
        for (int j = 0; j < 16; ++j)
          a[j] = fmaf(__ldcg(hp + r + j), __ldg(wp + (size_t)(r + j) * WCOLS), a[j]);
      }
      float s = 0.0f;
#pragma unroll
      for (int j = 0; j < 16; ++j) s += a[j];
      g_ghp[ci * WCOLS + col] = s + __ldg(bc + ci * 3072 + WCOLS + col);
    }
  }
}

// =====================================================================
// GRU0 kernel: 16-CTA cluster, weights mostly in REGISTERS,
// last k-quarter in SMEM, DSMEM h-broadcast per step.
// =====================================================================
// SMEM: swA [32u][3g][384k] staging+persistent first 3 quarters? No:
//   swA (144KB) is staging for reg load only; sw3 (48KB) persists for c=3.
#define SWA_FLOATS (32 * 3 * 384)
#define SW3_FLOATS (32 * 3 * 128)
#define GRU0_SMEM ((SWA_FLOATS + SW3_FLOATS + 2 * WU + WU) * 4)

__global__ void __launch_bounds__(GT, 1) gru0_kernel(
    const float *__restrict__ lin, const float *__restrict__ k0,
    const float *__restrict__ rk0, const float *__restrict__ b0,
    float *__restrict__ lout)
{
  extern __shared__ float sm[];
  float *swA = sm;                        // [u][g][k<384]  (staging)
  float *sw3 = sm + SWA_FLOATS;           // [u][g][k-384]  (persistent)
  float *sh  = sw3 + SW3_FLOATS;          // [2][512] double-buffered h
  float *sx0 = sh + 2 * WU;               // [512]

  unsigned rank;
  asm("mov.u32 %0, %%cluster_ctarank;" : "=r"(rank));
  const int tid = threadIdx.x, warp = tid >> 5, lane = tid & 31;
  const int base = (int)rank * 32;

  for (int i = tid; i < WU; i += GT) sx0[i] = __ldg(lin + 16 * i);
  for (int i = tid; i < 2 * WU; i += GT) sh[i] = 0.0f;
  // stage this CTA's 96 rec columns into SMEM, transposed to [u][g][k]
  for (int idx = tid; idx < 96 * WU; idx += GT) {
    int k = idx / 96, c2 = idx - k * 96;
    int g = c2 >> 5, u = c2 & 31;
    float w = __ldg(rk0 + (size_t)k * WCOLS + g * WU + base + u);
    if (k < 384) swA[(u * 3 + g) * 384 + k] = w;
    else         sw3[(u * 3 + g) * 128 + (k - 384)] = w;
  }

  // per-lane unit: lanes 0-15 -> unit 2*warp, lanes 16-31 -> unit 2*warp+1
  const bool hi = (lane >= 16);
  const int u0 = 2 * warp, u1 = 2 * warp + 1;
  const int gu = base + u0 + (hi ? 1 : 0);
  const float kz  = __ldg(k0 + gu);
  const float kr  = __ldg(k0 + WU + gu);
  const float kn  = __ldg(k0 + 2 * WU + gu);
  const float cbz = __ldg(b0 + gu) + __ldg(b0 + WCOLS + gu);
  const float cbr = __ldg(b0 + WU + gu) + __ldg(b0 + WCOLS + WU + gu);
  const float bin = __ldg(b0 + 2 * WU + gu);
  const float brn = __ldg(b0 + WCOLS + 2 * WU + gu);

  __syncthreads();

  // pull c=0..2 weight quarters into registers: W[c][unit][gate] = ulonglong2
  ulonglong2 W[3][2][3];
#pragma unroll
  for (int c = 0; c < 3; ++c) {
#pragma unroll
    for (int un = 0; un < 2; ++un) {
#pragma unroll
      for (int g = 0; g < 3; ++g) {
        W[c][un][g] = *(const ulonglong2 *)(
            swA + ((u0 + un) * 3 + g) * 384 + c * 128 + lane * 4);
      }
    }
  }

  const float *p3_0 = sw3 + (u0 * 3) * 128 + lane * 4;  // unit0 gates z,r,n
  const float *p3_1 = sw3 + (u1 * 3) * 128 + lane * 4;
  const uint32_t sh_u32 = (uint32_t)__cvta_generic_to_shared(sh);
  const unsigned trank = lane & 15;

  cluster_sync_();

  int cur = 0;
  for (int t = 0; t < WU; ++t) {
    const float *hb = sh + cur * WU;
    u64 az0 = 0, ar0 = 0, an0 = 0, az1 = 0, ar1 = 0, an1 = 0;
#pragma unroll
    for (int c = 0; c < 3; ++c) {
      ulonglong2 hv = *(const ulonglong2 *)(hb + c * 128 + lane * 4);
      ffma2(az0, hv.x, W[c][0][0].x); ffma2(az0, hv.y, W[c][0][0].y);
      ffma2(ar0, hv.x, W[c][0][1].x); ffma2(ar0, hv.y, W[c][0][1].y);
      ffma2(an0, hv.x, W[c][0][2].x); ffma2(an0, hv.y, W[c][0][2].y);
      ffma2(az1, hv.x, W[c][1][0].x); ffma2(az1, hv.y, W[c][1][0].y);
      ffma2(ar1, hv.x, W[c][1][1].x); ffma2(ar1, hv.y, W[c][1][1].y);
      ffma2(an1, hv.x, W[c][1][2].x); ffma2(an1, hv.y, W[c][1][2].y);
    }
    {
      ulonglong2 hv = *(const ulonglong2 *)(hb + 384 + lane * 4);
      ulonglong2 wz0 = *(const ulonglong2 *)(p3_0);
      ulonglong2 wr0 = *(const ulonglong2 *)(p3_0 + 128);
      ulonglong2 wn0 = *(const ulonglong2 *)(p3_0 + 256);
      ulonglong2 wz1 = *(const ulonglong2 *)(p3_1);
      ulonglong2 wr1 = *(const ulonglong2 *)(p3_1 + 128);
      ulonglong2 wn1 = *(const ulonglong2 *)(p3_1 + 256);
      ffma2(az0, hv.x, wz0.x); ffma2(az0, hv.y, wz0.y);
      ffma2(ar0, hv.x, wr0.x); ffma2(ar0, hv.y, wr0.y);
      ffma2(an0, hv.x, wn0.x); ffma2(an0, hv.y, wn0.y);
      ffma2(az1, hv.x, wz1.x); ffma2(az1, hv.y, wz1.y);
      ffma2(ar1, hv.x, wr1.x); ffma2(ar1, hv.y, wr1.y);
      ffma2(an1, hv.x, wn1.x); ffma2(an1, hv.y, wn1.y);
    }
    float dz = pair_reduce(hsum2(az0), hsum2(az1), hi);
    float dr = pair_reduce(hsum2(ar0), hsum2(ar1), hi);
    float dn = pair_reduce(hsum2(an0), hsum2(an1), hi);

    float xt = sx0[t];
    float z  = sigf_fast(fmaf(xt, kz, cbz) + dz);
    float r  = sigf_fast(fmaf(xt, kr, cbr) + dr);
    float hh = tanhf_fast(fmaf(xt, kn, bin) + r * (dn + brn));
    float hold = hb[gu];
    float hnew = hh + z * (hold - hh);

    if (t < WU - 1) {
      uint32_t laddr = sh_u32 + ((unsigned)((cur ^ 1) * WU + gu) << 2);
      st_cluster(laddr, trank, hnew);   // broadcast to all 16 CTAs (incl. self)
      cluster_sync_();
    } else {
      if ((lane & 15) == 0) lout[gu] = hnew;  // y0
    }
    cur ^= 1;
  }
}

// =====================================================================
// Chain kernel (96 CTAs persistent): 15 serial 2-step GRUs
// =====================================================================
__global__ void __launch_bounds__(NT, 1) chain_kernel(
    float *__restrict__ lout, const float *__restrict__ kc,
    const float *__restrict__ bc)
{
  __shared__ float sm_part[NW * 32];
  const int bid = blockIdx.x, tid = threadIdx.x;
  const int warp = tid >> 5, lane = tid & 31;
  unsigned gen = *(volatile unsigned *)&g_gen;

  for (int ci = 0; ci < 15; ++ci) {
    const float *yprev = lout + ci * WU;
    // pass1: gpart[half][col] = partial of y_prev . kc[ci][:,col]
    {
      int cb = bid >> 1, half = bid & 1;
      int col = cb * 32 + lane;
      const float *wp = kc + (size_t)ci * (WU * WCOLS) + col;
      float acc = 0.0f;
      for (int r0 = warp; r0 < 256; r0 += NW) {
        int r = half * 256 + r0;
        acc = fmaf(__ldcg(yprev + r), __ldg(wp + r * WCOLS), acc);
      }
      sm_part[warp * 32 + lane] = acc;
      __syncthreads();
      if (warp == 0) {
        float s = 0.0f;
#pragma unroll
        for (int w2 = 0; w2 < NW; ++w2) s += sm_part[w2 * 32 + lane];
        g_gpart[half * WCOLS + col] = s;
      }
    }
    grid_sync(gen, GC);
    // pass2: gates + y
    {
      int u = bid * NT + tid;
      if (u < WU) {
        float gxz = __ldcg(g_gpart + u) + __ldcg(g_gpart + WCOLS + u) +
                    __ldg(bc + ci * 3072 + u);
        float gxr = __ldcg(g_gpart + WU + u) + __ldcg(g_gpart + WCOLS + WU + u) +
                    __ldg(bc + ci * 3072 + WU + u);
        float gxh = __ldcg(g_gpart + 2 * WU + u) + __ldcg(g_gpart + WCOLS + 2 * WU + u) +
                    __ldg(bc + ci * 3072 + 2 * WU + u);
        float ghz = __ldcg(g_ghp + ci * WCOLS + u);
        float ghr = __ldcg(g_ghp + ci * WCOLS + WU + u);
        float ghn = __ldcg(g_ghp + ci * WCOLS + 2 * WU + u);
        float h1v = __ldcg(g_h1 + ci * WU + u);
        float z = sigmoidf_(gxz + ghz);
        float r = sigmoidf_(gxr + ghr);
        float hh = tanhf_(gxh + r * ghn);
        lout[(ci + 1) * WU + u] = z * h1v + (1.0f - z) * hh;
      }
    }
    grid_sync(gen, GC);
  }
}

// =====================================================================
// Host launcher
// =====================================================================
extern "C" void kernel_launch(void *const *d_in, const int *in_sizes, int n_in,
                              void *d_out, int out_size) {
  (void)in_sizes; (void)n_in; (void)out_size;
  const float *x = (const float *)d_in[0];
  const float *K0[3]  = {(const float *)d_in[1],  (const float *)d_in[7],  (const float *)d_in[13]};
  const float *RK0[3] = {(const float *)d_in[2],  (const float *)d_in[8],  (const float *)d_in[14]};
  const float *B0[3]  = {(const float *)d_in[3],  (const float *)d_in[9],  (const float *)d_in[15]};
  const float *KC[3]  = {(const float *)d_in[4],  (const float *)d_in[10], (const float *)d_in[16]};
  const float *RKC[3] = {(const float *)d_in[5],  (const float *)d_in[11], (const float *)d_in[17]};
  const float *BC[3]  = {(const float *)d_in[6],  (const float *)d_in[12], (const float *)d_in[18]};

  float *pA = nullptr, *pB = nullptr;
  cudaGetSymbolAddress((void **)&pA, g_bufA);
  cudaGetSymbolAddress((void **)&pB, g_bufB);

  cudaFuncSetAttribute(gru0_kernel, cudaFuncAttributeMaxDynamicSharedMemorySize, GRU0_SMEM);
  cudaFuncSetAttribute(gru0_kernel, cudaFuncAttributeNonPortableClusterSizeAllowed, 1);

  const float *LIN[3] = {x, pA, pB};
  float *LOUT[3] = {pA, pB, (float *)d_out};

  for (int l = 0; l < 3; ++l) {
    phases_kernel<<<GP, NT>>>(LIN[l], KC[l], RKC[l], BC[l]);

    cudaLaunchConfig_t cfg = {};
    cfg.gridDim = dim3(CL, 1, 1);
    cfg.blockDim = dim3(GT, 1, 1);
    cfg.dynamicSmemBytes = GRU0_SMEM;
    cfg.stream = 0;
    cudaLaunchAttribute attrs[1];
    attrs[0].id = cudaLaunchAttributeClusterDimension;
    attrs[0].val.clusterDim = {CL, 1, 1};
    cfg.attrs = attrs;
    cfg.numAttrs = 1;
    cudaLaunchKernelEx(&cfg, gru0_kernel, LIN[l], K0[l], RK0[l], B0[l], LOUT[l]);

    chain_kernel<<<GC, NT>>>(LOUT[l], KC[l], BC[l]);
  }
}

// round 5
// speedup vs baseline: 2.0147x; 1.1916x over previous
#include <cuda_runtime.h>
#include <cstdint>

#define NT 384
#define NW 12
#define WU 512
#define WCOLS 1536
#define GP 128   // phases grid
#define GC 96    // chain grid
#define CL 16    // GRU0 cluster size
#define GT 512   // GRU0 threads per CTA

typedef unsigned long long u64;

// ---------------- device scratch (static, no allocation) ----------------
__device__ float g_bufA[16 * WU];
__device__ float g_bufB[16 * WU];
__device__ float g_h1[15 * WU];
__device__ float g_ghp[15 * WCOLS];
__device__ float g_gxc[15 * WCOLS];
__device__ float g_gpart[2 * WCOLS];
__device__ unsigned g_count;
__device__ unsigned g_gen;

// Grid-wide barrier among nct co-resident CTAs. Generation continues
// monotonically across kernel launches (wrap-safe signed compare).
__device__ __forceinline__ void grid_sync(unsigned &gen, unsigned nct) {
  unsigned next = gen + 1u;
  __threadfence();
  __syncthreads();
  if (threadIdx.x == 0) {
    if (atomicAdd(&g_count, 1u) == nct - 1u) {
      atomicExch(&g_count, 0u);
      __threadfence();
      atomicExch(&g_gen, next);
    } else {
      while ((int)(*(volatile unsigned *)&g_gen - next) < 0) { }
    }
  }
  gen = next;
  __syncthreads();
}

__device__ __forceinline__ float sigmoidf_(float x) {
  return 1.0f / (1.0f + __expf(-x));
}
__device__ __forceinline__ float tanhf_(float x) {
  float ax = fabsf(x);
  float e = __expf(-2.0f * ax);
  float t = (1.0f - e) / (1.0f + e);
  return copysignf(t, x);
}
__device__ __forceinline__ float sigf_fast(float x) {
  return __fdividef(1.0f, 1.0f + __expf(-x));
}
__device__ __forceinline__ float tanhf_fast(float x) {
  float ax = fabsf(x);
  float e = __expf(-2.0f * ax);
  float t = __fdividef(1.0f - e, 1.0f + e);
  return copysignf(t, x);
}

// ---------------- Blackwell helpers ----------------
__device__ __forceinline__ void ffma2(u64 &acc, u64 a, u64 b) {
  asm("fma.rn.f32x2 %0, %1, %2, %0;" : "+l"(acc) : "l"(a), "l"(b));
}
__device__ __forceinline__ float hsum2(u64 v) {
  float lo, hi;
  asm("mov.b64 {%0,%1}, %2;" : "=f"(lo), "=f"(hi) : "l"(v));
  return lo + hi;
}
// Paired half-warp reduction: lo lanes (0-15) return full-warp sum of d0,
// hi lanes (16-31) return full-warp sum of d1. 5 shuffle levels total.
__device__ __forceinline__ float pair_reduce(float d0, float d1, bool hi) {
  float own = hi ? d1 : d0;
  float oth = hi ? d0 : d1;
  float s = own + __shfl_xor_sync(0xffffffffu, oth, 16);
#pragma unroll
  for (int o = 8; o; o >>= 1) s += __shfl_xor_sync(0xffffffffu, s, o);
  return s;
}
__device__ __forceinline__ uint32_t mapa_u32(uint32_t laddr, unsigned rank) {
  uint32_t raddr;
  asm("mapa.shared::cluster.u32 %0, %1, %2;" : "=r"(raddr) : "r"(laddr), "r"(rank));
  return raddr;
}
// Remote store with mbarrier transaction completion (sm_90+).
__device__ __forceinline__ void st_async_f32(uint32_t raddr, uint32_t rmbar, float v) {
  asm volatile(
      "st.async.shared::cluster.mbarrier::complete_tx::bytes.b32 [%0], %1, [%2];"
      :: "r"(raddr), "r"(__float_as_uint(v)), "r"(rmbar) : "memory");
}
__device__ __forceinline__ void mbar_init(uint32_t mbar, unsigned cnt) {
  asm volatile("mbarrier.init.shared.b64 [%0], %1;" :: "r"(mbar), "r"(cnt) : "memory");
}
__device__ __forceinline__ void mbar_expect_tx(uint32_t mbar, unsigned bytes) {
  asm volatile("mbarrier.arrive.expect_tx.shared.b64 _, [%0], %1;"
               :: "r"(mbar), "r"(bytes) : "memory");
}
__device__ __forceinline__ void mbar_wait(uint32_t mbar, uint32_t parity) {
  uint32_t done;
  asm volatile(
      "{\n\t.reg .pred p;\n\t"
      "mbarrier.try_wait.parity.acquire.cta.shared::cta.b64 p, [%1], %2;\n\t"
      "selp.b32 %0, 1, 0, p;\n\t}"
      : "=r"(done) : "r"(mbar), "r"(parity) : "memory");
  if (!done) {
    asm volatile(
        "{\n\t.reg .pred P1;\n\t"
        "WAIT_LOOP_%=:\n\t"
        "mbarrier.try_wait.parity.acquire.cta.shared::cta.b64 P1, [%0], %1, 0x989680;\n\t"
        "@P1 bra.uni WAIT_DONE_%=;\n\t"
        "bra.uni WAIT_LOOP_%=;\n\t"
        "WAIT_DONE_%=:\n\t}"
        :: "r"(mbar), "r"(parity) : "memory");
  }
}
__device__ __forceinline__ void cluster_sync_() {
  asm volatile("barrier.cluster.arrive.aligned;" ::: "memory");
  asm volatile("barrier.cluster.wait.aligned;" ::: "memory");
}

// =====================================================================
// Phases kernel (full grid, 128 CTAs): gxc -> h1 -> ghp for all 15 chain GRUs
// Each column job split into 2 row-halves (2 warps), combined in SMEM.
// =====================================================================
__global__ void __launch_bounds__(NT, 1) phases_kernel(
    const float *__restrict__ lin, const float *__restrict__ kc,
    const float *__restrict__ rkc, const float *__restrict__ bc)
{
  __shared__ float sm_x1[WU];
  __shared__ float sm_part[NW][32];
  const int bid = blockIdx.x, tid = threadIdx.x;
  const int warp = tid >> 5, lane = tid & 31;
  unsigned gen = *(volatile unsigned *)&g_gen;

  for (int i = tid; i < WU; i += NT) sm_x1[i] = __ldcg(lin + i * 16 + 1);
  __syncthreads();

  const int wg = bid * NW + warp;        // 0..1535
  const int job = wg >> 1, half = wg & 1;
  const bool active = (job < 720);
  int ci = 0, col = 0;
  if (active) { ci = job / 48; col = (job - ci * 48) * 32 + lane; }

  // phase A: gxc[ci][col] = x1 . kc[ci][:,col] + b_i  (row-split by half)
  {
    float s = 0.0f;
    if (active) {
      const float *wp = kc + (size_t)ci * (WU * WCOLS) + (size_t)(half * 256) * WCOLS + col;
      float a[16];
#pragma unroll
      for (int j = 0; j < 16; ++j) a[j] = 0.0f;
      for (int r = 0; r < 256; r += 16) {
#pragma unroll
        for (int j = 0; j < 16; ++j)
          a[j] = fmaf(sm_x1[half * 256 + r + j], __ldg(wp + (size_t)(r + j) * WCOLS), a[j]);
      }
#pragma unroll
      for (int j = 0; j < 16; ++j) s += a[j];
    }
    sm_part[warp][lane] = s;
    __syncthreads();
    if (active && (warp & 1) == 0) {
      float tot = sm_part[warp][lane] + sm_part[warp + 1][lane];
      g_gxc[ci * WCOLS + col] = tot + __ldg(bc + ci * 3072 + col);
    }
  }
  grid_sync(gen, GP);

  // h1 pointwise (chain step 1, h=0)
  {
    int e = bid * NT + tid;
    if (e < 15 * WU) {
      int c2 = e >> 9, u = e & (WU - 1);
      float gz = __ldcg(g_gxc + c2 * WCOLS + u);
      float gr = __ldcg(g_gxc + c2 * WCOLS + WU + u);
      float gn = __ldcg(g_gxc + c2 * WCOLS + 2 * WU + u);
      float brz = __ldg(bc + c2 * 3072 + WCOLS + u);
      float brr = __ldg(bc + c2 * 3072 + WCOLS + WU + u);
      float brn = __ldg(bc + c2 * 3072 + WCOLS + 2 * WU + u);
      float z = sigmoidf_(gz + brz);
      float r = sigmoidf_(gr + brr);
      float hh = tanhf_(gn + r * brn);
      g_h1[e] = (1.0f - z) * hh;
    }
  }
  grid_sync(gen, GP);

  // phase B: ghp[ci][col] = h1[ci] . rkc[ci][:,col] + b_r  (row-split by half)
  {
    float s = 0.0f;
    if (active) {
      const float *wp = rkc + (size_t)ci * (WU * WCOLS) + (size_t)(half * 256) * WCOLS + col;
      const float *hp = g_h1 + ci * WU + half * 256;
      float a[16];
#pragma unroll
      for (int j = 0; j < 16; ++j) a[j] = 0.0f;
      for (int r = 0; r < 256; r += 16) {
#pragma unroll
        for (int j = 0; j < 16; ++j)
          a[j] = fmaf(__ldcg(hp + r + j), __ldg(wp + (size_t)(r + j) * WCOLS), a[j]);
      }
#pragma unroll
      for (int j = 0; j < 16; ++j) s += a[j];
    }
    sm_part[warp][lane] = s;
    __syncthreads();
    if (active && (warp & 1) == 0) {
      float tot = sm_part[warp][lane] + sm_part[warp + 1][lane];
      g_ghp[ci * WCOLS + col] = tot + __ldg(bc + ci * 3072 + WCOLS + col);
    }
  }
}

// =====================================================================
// GRU0 kernel: 16-CTA cluster, weights mostly in registers, last quarter
// in SMEM. Per-step sync via st.async + tx-counted mbarrier (NO cluster
// barrier in the loop). Double-buffered h: WAR-safe because mbar[q] full
// implies every thread finished step t, hence finished reading buffer p.
// =====================================================================
#define SWA_FLOATS (32 * 3 * 384)
#define SW3_FLOATS (32 * 3 * 128)
#define GRU0_SMEM ((SWA_FLOATS + SW3_FLOATS + 2 * WU + WU + 4) * 4)

__global__ void __launch_bounds__(GT, 1) gru0_kernel(
    const float *__restrict__ lin, const float *__restrict__ k0,
    const float *__restrict__ rk0, const float *__restrict__ b0,
    float *__restrict__ lout)
{
  extern __shared__ float sm[];
  float *swA = sm;                        // staging for reg-resident quarters
  float *sw3 = sm + SWA_FLOATS;           // persistent 4th quarter
  float *sh  = sw3 + SW3_FLOATS;          // [2][512] double-buffered h
  float *sx0 = sh + 2 * WU;               // [512]
  // mbar[2] lives after sx0 (8B aligned)

  unsigned rank;
  asm("mov.u32 %0, %%cluster_ctarank;" : "=r"(rank));
  const int tid = threadIdx.x, warp = tid >> 5, lane = tid & 31;
  const int base = (int)rank * 32;

  const uint32_t sm_u32 = (uint32_t)__cvta_generic_to_shared(sm);
  const uint32_t sh_u32 = sm_u32 + (SWA_FLOATS + SW3_FLOATS) * 4;
  const uint32_t mbar_u32 = sh_u32 + (2 * WU + WU) * 4;

  for (int i = tid; i < WU; i += GT) sx0[i] = __ldg(lin + 16 * i);
  for (int i = tid; i < 2 * WU; i += GT) sh[i] = 0.0f;
  // stage this CTA's 96 rec columns into SMEM, transposed to [u][g][k]
  for (int idx = tid; idx < 96 * WU; idx += GT) {
    int k = idx / 96, c2 = idx - k * 96;
    int g = c2 >> 5, u = c2 & 31;
    float w = __ldg(rk0 + (size_t)k * WCOLS + g * WU + base + u);
    if (k < 384) swA[(u * 3 + g) * 384 + k] = w;
    else         sw3[(u * 3 + g) * 128 + (k - 384)] = w;
  }
  if (tid == 0) {
    mbar_init(mbar_u32, 1);
    mbar_init(mbar_u32 + 8, 1);
    mbar_expect_tx(mbar_u32, 2048);      // phase 0: filled by step-1 stores
    mbar_expect_tx(mbar_u32 + 8, 2048);  // phase 0: filled by step-0 stores
  }

  // per-lane unit: lanes 0-15 -> unit 2*warp, lanes 16-31 -> unit 2*warp+1
  const bool hi = (lane >= 16);
  const int u0 = 2 * warp, u1 = 2 * warp + 1;
  const int gu = base + u0 + (hi ? 1 : 0);
  const float kz  = __ldg(k0 + gu);
  const float kr  = __ldg(k0 + WU + gu);
  const float kn  = __ldg(k0 + 2 * WU + gu);
  const float cbz = __ldg(b0 + gu) + __ldg(b0 + WCOLS + gu);
  const float cbr = __ldg(b0 + WU + gu) + __ldg(b0 + WCOLS + WU + gu);
  const float bin = __ldg(b0 + 2 * WU + gu);
  const float brn = __ldg(b0 + WCOLS + 2 * WU + gu);

  __syncthreads();

  // pull c=0..2 weight quarters into registers
  ulonglong2 W[3][2][3];
#pragma unroll
  for (int c = 0; c < 3; ++c) {
#pragma unroll
    for (int un = 0; un < 2; ++un) {
#pragma unroll
      for (int g = 0; g < 3; ++g) {
        W[c][un][g] = *(const ulonglong2 *)(
            swA + ((u0 + un) * 3 + g) * 384 + c * 128 + lane * 4);
      }
    }
  }

  const float *p3_0 = sw3 + (u0 * 3) * 128 + lane * 4;
  const float *p3_1 = sw3 + (u1 * 3) * 128 + lane * 4;

  // precomputed remote addresses (fixed target rank per thread)
  const unsigned trank = lane & 15;
  uint32_t ra[2], rm[2];
#pragma unroll
  for (int b = 0; b < 2; ++b) {
    ra[b] = mapa_u32(sh_u32 + ((unsigned)(b * WU + gu) << 2), trank);
    rm[b] = mapa_u32(mbar_u32 + 8 * b, trank);
  }
  uint32_t ph0 = 0, ph1 = 0;

  cluster_sync_();  // all mbars initialized, all h buffers zeroed

  for (int t = 0; t < WU; ++t) {
    const int p = t & 1;
    if (t) {
      const uint32_t mb = mbar_u32 + 8 * p;
      if (p) { mbar_wait(mb, ph1); ph1 ^= 1; }
      else   { mbar_wait(mb, ph0); ph0 ^= 1; }
      if (tid == 0) mbar_expect_tx(mb, 2048);  // re-arm for next fill of p
    }
    const float *hb = sh + p * WU;
    u64 az0 = 0, ar0 = 0, an0 = 0, az1 = 0, ar1 = 0, an1 = 0;
#pragma unroll
    for (int c = 0; c < 3; ++c) {
      ulonglong2 hv = *(const ulonglong2 *)(hb + c * 128 + lane * 4);
      ffma2(az0, hv.x, W[c][0][0].x); ffma2(az0, hv.y, W[c][0][0].y);
      ffma2(ar0, hv.x, W[c][0][1].x); ffma2(ar0, hv.y, W[c][0][1].y);
      ffma2(an0, hv.x, W[c][0][2].x); ffma2(an0, hv.y, W[c][0][2].y);
      ffma2(az1, hv.x, W[c][1][0].x); ffma2(az1, hv.y, W[c][1][0].y);
      ffma2(ar1, hv.x, W[c][1][1].x); ffma2(ar1, hv.y, W[c][1][1].y);
      ffma2(an1, hv.x, W[c][1][2].x); ffma2(an1, hv.y, W[c][1][2].y);
    }
    {
      ulonglong2 hv = *(const ulonglong2 *)(hb + 384 + lane * 4);
      ulonglong2 wz0 = *(const ulonglong2 *)(p3_0);
      ulonglong2 wr0 = *(const ulonglong2 *)(p3_0 + 128);
      ulonglong2 wn0 = *(const ulonglong2 *)(p3_0 + 256);
      ulonglong2 wz1 = *(const ulonglong2 *)(p3_1);
      ulonglong2 wr1 = *(const ulonglong2 *)(p3_1 + 128);
      ulonglong2 wn1 = *(const ulonglong2 *)(p3_1 + 256);
      ffma2(az0, hv.x, wz0.x); ffma2(az0, hv.y, wz0.y);
      ffma2(ar0, hv.x, wr0.x); ffma2(ar0, hv.y, wr0.y);
      ffma2(an0, hv.x, wn0.x); ffma2(an0, hv.y, wn0.y);
      ffma2(az1, hv.x, wz1.x); ffma2(az1, hv.y, wz1.y);
      ffma2(ar1, hv.x, wr1.x); ffma2(ar1, hv.y, wr1.y);
      ffma2(an1, hv.x, wn1.x); ffma2(an1, hv.y, wn1.y);
    }
    float dz = pair_reduce(hsum2(az0), hsum2(az1), hi);
    float dr = pair_reduce(hsum2(ar0), hsum2(ar1), hi);
    float dn = pair_reduce(hsum2(an0), hsum2(an1), hi);

    float xt = sx0[t];
    float z  = sigf_fast(fmaf(xt, kz, cbz) + dz);
    float r  = sigf_fast(fmaf(xt, kr, cbr) + dr);
    float hh = tanhf_fast(fmaf(xt, kn, bin) + r * (dn + brn));
    float hold = hb[gu];
    float hnew = hh + z * (hold - hh);

    // Ensure tid0's expect_tx (and all reads of buffer p) precede any of this
    // CTA's stores -- our stores gate every other CTA's entry into step t+1.
    __syncthreads();

    if (t < WU - 1) {
      st_async_f32(ra[p ^ 1], rm[p ^ 1], hnew);
    } else {
      if ((lane & 15) == 0) lout[gu] = hnew;  // y0
    }
  }
}

// =====================================================================
// Chain kernel (96 CTAs persistent): 15 serial 2-step GRUs
// =====================================================================
__global__ void __launch_bounds__(NT, 1) chain_kernel(
    float *__restrict__ lout, const float *__restrict__ kc,
    const float *__restrict__ bc)
{
  __shared__ float sm_part[NW * 32];
  const int bid = blockIdx.x, tid = threadIdx.x;
  const int warp = tid >> 5, lane = tid & 31;
  unsigned gen = *(volatile unsigned *)&g_gen;

  for (int ci = 0; ci < 15; ++ci) {
    const float *yprev = lout + ci * WU;
    // pass1: gpart[half][col] = partial of y_prev . kc[ci][:,col]
    {
      int cb = bid >> 1, half = bid & 1;
      int col = cb * 32 + lane;
      const float *wp = kc + (size_t)ci * (WU * WCOLS) + col;
      float acc = 0.0f;
      for (int r0 = warp; r0 < 256; r0 += NW) {
        int r = half * 256 + r0;
        acc = fmaf(__ldcg(yprev + r), __ldg(wp + r * WCOLS), acc);
      }
      sm_part[warp * 32 + lane] = acc;
      __syncthreads();
      if (warp == 0) {
        float s = 0.0f;
#pragma unroll
        for (int w2 = 0; w2 < NW; ++w2) s += sm_part[w2 * 32 + lane];
        g_gpart[half * WCOLS + col] = s;
      }
    }
    grid_sync(gen, GC);
    // pass2: gates + y
    {
      int u = bid * NT + tid;
      if (u < WU) {
        float gxz = __ldcg(g_gpart + u) + __ldcg(g_gpart + WCOLS + u) +
                    __ldg(bc + ci * 3072 + u);
        float gxr = __ldcg(g_gpart + WU + u) + __ldcg(g_gpart + WCOLS + WU + u) +
                    __ldg(bc + ci * 3072 + WU + u);
        float gxh = __ldcg(g_gpart + 2 * WU + u) + __ldcg(g_gpart + WCOLS + 2 * WU + u) +
                    __ldg(bc + ci * 3072 + 2 * WU + u);
        float ghz = __ldcg(g_ghp + ci * WCOLS + u);
        float ghr = __ldcg(g_ghp + ci * WCOLS + WU + u);
        float ghn = __ldcg(g_ghp + ci * WCOLS + 2 * WU + u);
        float h1v = __ldcg(g_h1 + ci * WU + u);
        float z = sigmoidf_(gxz + ghz);
        float r = sigmoidf_(gxr + ghr);
        float hh = tanhf_(gxh + r * ghn);
        lout[(ci + 1) * WU + u] = z * h1v + (1.0f - z) * hh;
      }
    }
    grid_sync(gen, GC);
  }
}

// =====================================================================
// Host launcher
// =====================================================================
extern "C" void kernel_launch(void *const *d_in, const int *in_sizes, int n_in,
                              void *d_out, int out_size) {
  (void)in_sizes; (void)n_in; (void)out_size;
  const float *x = (const float *)d_in[0];
  const float *K0[3]  = {(const float *)d_in[1],  (const float *)d_in[7],  (const float *)d_in[13]};
  const float *RK0[3] = {(const float *)d_in[2],  (const float *)d_in[8],  (const float *)d_in[14]};
  const float *B0[3]  = {(const float *)d_in[3],  (const float *)d_in[9],  (const float *)d_in[15]};
  const float *KC[3]  = {(const float *)d_in[4],  (const float *)d_in[10], (const float *)d_in[16]};
  const float *RKC[3] = {(const float *)d_in[5],  (const float *)d_in[11], (const float *)d_in[17]};
  const float *BC[3]  = {(const float *)d_in[6],  (const float *)d_in[12], (const float *)d_in[18]};

  float *pA = nullptr, *pB = nullptr;
  cudaGetSymbolAddress((void **)&pA, g_bufA);
  cudaGetSymbolAddress((void **)&pB, g_bufB);

  cudaFuncSetAttribute(gru0_kernel, cudaFuncAttributeMaxDynamicSharedMemorySize, GRU0_SMEM);
  cudaFuncSetAttribute(gru0_kernel, cudaFuncAttributeNonPortableClusterSizeAllowed, 1);

  const float *LIN[3] = {x, pA, pB};
  float *LOUT[3] = {pA, pB, (float *)d_out};

  for (int l = 0; l < 3; ++l) {
    phases_kernel<<<GP, NT>>>(LIN[l], KC[l], RKC[l], BC[l]);

    cudaLaunchConfig_t cfg = {};
    cfg.gridDim = dim3(CL, 1, 1);
    cfg.blockDim = dim3(GT, 1, 1);
    cfg.dynamicSmemBytes = GRU0_SMEM;
    cfg.stream = 0;
    cudaLaunchAttribute attrs[1];
    attrs[0].id = cudaLaunchAttributeClusterDimension;
    attrs[0].val.clusterDim = {CL, 1, 1};
    cfg.attrs = attrs;
    cfg.numAttrs = 1;
    cudaLaunchKernelEx(&cfg, gru0_kernel, LIN[l], K0[l], RK0[l], B0[l], LOUT[l]);

    chain_kernel<<<GC, NT>>>(LOUT[l], KC[l], BC[l]);
  }
}

// round 6
// speedup vs baseline: 2.0234x; 1.0043x over previous
#include <cuda_runtime.h>
#include <cstdint>

#define NT 384
#define NW 12
#define WU 512
#define WCOLS 1536
#define GP 128   // phases grid
#define GC 96    // chain grid
#define CL 16    // GRU0 cluster size
#define GT 512   // GRU0 threads per CTA

typedef unsigned long long u64;

// ---------------- device scratch (static, no allocation) ----------------
__device__ float g_bufA[16 * WU];
__device__ float g_bufB[16 * WU];
__device__ float g_h1[15 * WU];
__device__ float g_ghp[15 * WCOLS];
__device__ float g_gxc[15 * WCOLS];
__device__ float g_gpart[2 * WCOLS];
__device__ unsigned g_count;
__device__ unsigned g_gen;

// Grid-wide barrier among nct co-resident CTAs. Generation continues
// monotonically across kernel launches (wrap-safe signed compare).
__device__ __forceinline__ void grid_sync(unsigned &gen, unsigned nct) {
  unsigned next = gen + 1u;
  __threadfence();
  __syncthreads();
  if (threadIdx.x == 0) {
    if (atomicAdd(&g_count, 1u) == nct - 1u) {
      atomicExch(&g_count, 0u);
      __threadfence();
      atomicExch(&g_gen, next);
    } else {
      while ((int)(*(volatile unsigned *)&g_gen - next) < 0) { }
    }
  }
  gen = next;
  __syncthreads();
}

__device__ __forceinline__ float sigmoidf_(float x) {
  return 1.0f / (1.0f + __expf(-x));
}
__device__ __forceinline__ float tanhf_(float x) {
  float ax = fabsf(x);
  float e = __expf(-2.0f * ax);
  float t = (1.0f - e) / (1.0f + e);
  return copysignf(t, x);
}
__device__ __forceinline__ float sigf_fast(float x) {
  return __fdividef(1.0f, 1.0f + __expf(-x));
}
__device__ __forceinline__ float tanhf_fast(float x) {
  float ax = fabsf(x);
  float e = __expf(-2.0f * ax);
  float t = __fdividef(1.0f - e, 1.0f + e);
  return copysignf(t, x);
}

// ---------------- Blackwell helpers ----------------
__device__ __forceinline__ void ffma2(u64 &acc, u64 a, u64 b) {
  asm("fma.rn.f32x2 %0, %1, %2, %0;" : "+l"(acc) : "l"(a), "l"(b));
}
__device__ __forceinline__ float hsum2(u64 v) {
  float lo, hi;
  asm("mov.b64 {%0,%1}, %2;" : "=f"(lo), "=f"(hi) : "l"(v));
  return lo + hi;
}
// Paired half-warp reduction: lo lanes (0-15) return full-warp sum of d0,
// hi lanes (16-31) return full-warp sum of d1. 5 shuffle levels total.
__device__ __forceinline__ float pair_reduce(float d0, float d1, bool hi) {
  float own = hi ? d1 : d0;
  float oth = hi ? d0 : d1;
  float s = own + __shfl_xor_sync(0xffffffffu, oth, 16);
#pragma unroll
  for (int o = 8; o; o >>= 1) s += __shfl_xor_sync(0xffffffffu, s, o);
  return s;
}
__device__ __forceinline__ uint32_t mapa_u32(uint32_t laddr, unsigned rank) {
  uint32_t raddr;
  asm("mapa.shared::cluster.u32 %0, %1, %2;" : "=r"(raddr) : "r"(laddr), "r"(rank));
  return raddr;
}
// Remote store with mbarrier transaction completion (sm_90+).
__device__ __forceinline__ void st_async_f32(uint32_t raddr, uint32_t rmbar, float v) {
  asm volatile(
      "st.async.shared::cluster.mbarrier::complete_tx::bytes.b32 [%0], %1, [%2];"
      :: "r"(raddr), "r"(__float_as_uint(v)), "r"(rmbar) : "memory");
}
__device__ __forceinline__ void mbar_init(uint32_t mbar, unsigned cnt) {
  asm volatile("mbarrier.init.shared.b64 [%0], %1;" :: "r"(mbar), "r"(cnt) : "memory");
}
__device__ __forceinline__ void mbar_expect_tx(uint32_t mbar, unsigned bytes) {
  asm volatile("mbarrier.arrive.expect_tx.shared.b64 _, [%0], %1;"
               :: "r"(mbar), "r"(bytes) : "memory");
}
__device__ __forceinline__ void mbar_wait(uint32_t mbar, uint32_t parity) {
  uint32_t done;
  asm volatile(
      "{\n\t.reg .pred p;\n\t"
      "mbarrier.try_wait.parity.acquire.cta.shared::cta.b64 p, [%1], %2;\n\t"
      "selp.b32 %0, 1, 0, p;\n\t}"
      : "=r"(done) : "r"(mbar), "r"(parity) : "memory");
  if (!done) {
    asm volatile(
        "{\n\t.reg .pred P1;\n\t"
        "WAIT_LOOP_%=:\n\t"
        "mbarrier.try_wait.parity.acquire.cta.shared::cta.b64 P1, [%0], %1, 0x989680;\n\t"
        "@P1 bra.uni WAIT_DONE_%=;\n\t"
        "bra.uni WAIT_LOOP_%=;\n\t"
        "WAIT_DONE_%=:\n\t}"
        :: "r"(mbar), "r"(parity) : "memory");
  }
}
__device__ __forceinline__ void cluster_sync_() {
  asm volatile("barrier.cluster.arrive.aligned;" ::: "memory");
  asm volatile("barrier.cluster.wait.aligned;" ::: "memory");
}

// =====================================================================
// Phases kernel (full grid, 128 CTAs): gxc -> h1 -> ghp for all 15 chain GRUs
// Each column job split into 2 row-halves (2 warps), combined in SMEM.
// =====================================================================
__global__ void __launch_bounds__(NT, 1) phases_kernel(
    const float *__restrict__ lin, const float *__restrict__ kc,
    const float *__restrict__ rkc, const float *__restrict__ bc)
{
  __shared__ float sm_x1[WU];
  __shared__ float sm_part[NW][32];
  const int bid = blockIdx.x, tid = threadIdx.x;
  const int warp = tid >> 5, lane = tid & 31;
  unsigned gen = *(volatile unsigned *)&g_gen;

  for (int i = tid; i < WU; i += NT) sm_x1[i] = __ldcg(lin + i * 16 + 1);
  __syncthreads();

  const int wg = bid * NW + warp;        // 0..1535
  const int job = wg >> 1, half = wg & 1;
  const bool active = (job < 720);
  int ci = 0, col = 0;
  if (active) { ci = job / 48; col = (job - ci * 48) * 32 + lane; }

  // phase A: gxc[ci][col] = x1 . kc[ci][:,col] + b_i  (row-split by half)
  {
    float s = 0.0f;
    if (active) {
      const float *wp = kc + (size_t)ci * (WU * WCOLS) + (size_t)(half * 256) * WCOLS + col;
      float a[16];
#pragma unroll
      for (int j = 0; j < 16; ++j) a[j] = 0.0f;
      for (int r = 0; r < 256; r += 16) {
#pragma unroll
        for (int j = 0; j < 16; ++j)
          a[j] = fmaf(sm_x1[half * 256 + r + j], __ldg(wp + (size_t)(r + j) * WCOLS), a[j]);
      }
#pragma unroll
      for (int j = 0; j < 16; ++j) s += a[j];
    }
    sm_part[warp][lane] = s;
    __syncthreads();
    if (active && (warp & 1) == 0) {
      float tot = sm_part[warp][lane] + sm_part[warp + 1][lane];
      g_gxc[ci * WCOLS + col] = tot + __ldg(bc + ci * 3072 + col);
    }
  }
  grid_sync(gen, GP);

  // h1 pointwise (chain step 1, h=0)
  {
    int e = bid * NT + tid;
    if (e < 15 * WU) {
      int c2 = e >> 9, u = e & (WU - 1);
      float gz = __ldcg(g_gxc + c2 * WCOLS + u);
      float gr = __ldcg(g_gxc + c2 * WCOLS + WU + u);
      float gn = __ldcg(g_gxc + c2 * WCOLS + 2 * WU + u);
      float brz = __ldg(bc + c2 * 3072 + WCOLS + u);
      float brr = __ldg(bc + c2 * 3072 + WCOLS + WU + u);
      float brn = __ldg(bc + c2 * 3072 + WCOLS + 2 * WU + u);
      float z = sigmoidf_(gz + brz);
      float r = sigmoidf_(gr + brr);
      float hh = tanhf_(gn + r * brn);
      g_h1[e] = (1.0f - z) * hh;
    }
  }
  grid_sync(gen, GP);

  // phase B: ghp[ci][col] = h1[ci] . rkc[ci][:,col] + b_r  (row-split by half)
  {
    float s = 0.0f;
    if (active) {
      const float *wp = rkc + (size_t)ci * (WU * WCOLS) + (size_t)(half * 256) * WCOLS + col;
      const float *hp = g_h1 + ci * WU + half * 256;
      float a[16];
#pragma unroll
      for (int j = 0; j < 16; ++j) a[j] = 0.0f;
      for (int r = 0; r < 256; r += 16) {
#pragma unroll
        for (int j = 0; j < 16; ++j)
          a[j] = fmaf(__ldcg(hp + r + j), __ldg(wp + (size_t)(r + j) * WCOLS), a[j]);
      }
#pragma unroll
      for (int j = 0; j < 16; ++j) s += a[j];
    }
    sm_part[warp][lane] = s;
    __syncthreads();
    if (active && (warp & 1) == 0) {
      float tot = sm_part[warp][lane] + sm_part[warp + 1][lane];
      g_ghp[ci * WCOLS + col] = tot + __ldg(bc + ci * 3072 + WCOLS + col);
    }
  }
}

// =====================================================================
// GRU0 kernel: 16-CTA cluster, weights mostly in registers, last quarter
// in SMEM. Per-step sync via st.async + tx-counted mbarrier (NO cluster
// barrier in the loop). Double-buffered h: WAR-safe because mbar[q] full
// implies every thread finished step t, hence finished reading buffer p.
// =====================================================================
#define SWA_FLOATS (32 * 3 * 384)
#define SW3_FLOATS (32 * 3 * 128)
#define GRU0_SMEM ((SWA_FLOATS + SW3_FLOATS + 2 * WU + WU + 4) * 4)

__global__ void __launch_bounds__(GT, 1) gru0_kernel(
    const float *__restrict__ lin, const float *__restrict__ k0,
    const float *__restrict__ rk0, const float *__restrict__ b0,
    float *__restrict__ lout)
{
  extern __shared__ float sm[];
  float *swA = sm;                        // staging for reg-resident quarters
  float *sw3 = sm + SWA_FLOATS;           // persistent 4th quarter
  float *sh  = sw3 + SW3_FLOATS;          // [2][512] double-buffered h
  float *sx0 = sh + 2 * WU;               // [512]
  // mbar[2] lives after sx0 (8B aligned)

  unsigned rank;
  asm("mov.u32 %0, %%cluster_ctarank;" : "=r"(rank));
  const int tid = threadIdx.x, warp = tid >> 5, lane = tid & 31;
  const int base = (int)rank * 32;

  const uint32_t sm_u32 = (uint32_t)__cvta_generic_to_shared(sm);
  const uint32_t sh_u32 = sm_u32 + (SWA_FLOATS + SW3_FLOATS) * 4;
  const uint32_t mbar_u32 = sh_u32 + (2 * WU + WU) * 4;

  for (int i = tid; i < WU; i += GT) sx0[i] = __ldg(lin + 16 * i);
  for (int i = tid; i < 2 * WU; i += GT) sh[i] = 0.0f;
  // stage this CTA's 96 rec columns into SMEM, transposed to [u][g][k]
  for (int idx = tid; idx < 96 * WU; idx += GT) {
    int k = idx / 96, c2 = idx - k * 96;
    int g = c2 >> 5, u = c2 & 31;
    float w = __ldg(rk0 + (size_t)k * WCOLS + g * WU + base + u);
    if (k < 384) swA[(u * 3 + g) * 384 + k] = w;
    else         sw3[(u * 3 + g) * 128 + (k - 384)] = w;
  }
  if (tid == 0) {
    mbar_init(mbar_u32, 1);
    mbar_init(mbar_u32 + 8, 1);
    mbar_expect_tx(mbar_u32, 2048);      // phase 0: filled by step-1 stores
    mbar_expect_tx(mbar_u32 + 8, 2048);  // phase 0: filled by step-0 stores
  }

  // per-lane unit: lanes 0-15 -> unit 2*warp, lanes 16-31 -> unit 2*warp+1
  const bool hi = (lane >= 16);
  const int u0 = 2 * warp, u1 = 2 * warp + 1;
  const int gu = base + u0 + (hi ? 1 : 0);
  const float kz  = __ldg(k0 + gu);
  const float kr  = __ldg(k0 + WU + gu);
  const float kn  = __ldg(k0 + 2 * WU + gu);
  const float cbz = __ldg(b0 + gu) + __ldg(b0 + WCOLS + gu);
  const float cbr = __ldg(b0 + WU + gu) + __ldg(b0 + WCOLS + WU + gu);
  const float bin = __ldg(b0 + 2 * WU + gu);
  const float brn = __ldg(b0 + WCOLS + 2 * WU + gu);

  __syncthreads();

  // pull c=0..2 weight quarters into registers
  ulonglong2 W[3][2][3];
#pragma unroll
  for (int c = 0; c < 3; ++c) {
#pragma unroll
    for (int un = 0; un < 2; ++un) {
#pragma unroll
      for (int g = 0; g < 3; ++g) {
        W[c][un][g] = *(const ulonglong2 *)(
            swA + ((u0 + un) * 3 + g) * 384 + c * 128 + lane * 4);
      }
    }
  }

  const float *p3_0 = sw3 + (u0 * 3) * 128 + lane * 4;
  const float *p3_1 = sw3 + (u1 * 3) * 128 + lane * 4;

  // precomputed remote addresses (fixed target rank per thread)
  const unsigned trank = lane & 15;
  uint32_t ra[2], rm[2];
#pragma unroll
  for (int b = 0; b < 2; ++b) {
    ra[b] = mapa_u32(sh_u32 + ((unsigned)(b * WU + gu) << 2), trank);
    rm[b] = mapa_u32(mbar_u32 + 8 * b, trank);
  }
  uint32_t ph0 = 0, ph1 = 0;

  cluster_sync_();  // all mbars initialized, all h buffers zeroed

  for (int t = 0; t < WU; ++t) {
    const int p = t & 1;
    if (t) {
      const uint32_t mb = mbar_u32 + 8 * p;
      if (p) { mbar_wait(mb, ph1); ph1 ^= 1; }
      else   { mbar_wait(mb, ph0); ph0 ^= 1; }
      if (tid == 0) mbar_expect_tx(mb, 2048);  // re-arm for next fill of p
    }
    const float *hb = sh + p * WU;
    u64 az0 = 0, ar0 = 0, an0 = 0, az1 = 0, ar1 = 0, an1 = 0;
#pragma unroll
    for (int c = 0; c < 3; ++c) {
      ulonglong2 hv = *(const ulonglong2 *)(hb + c * 128 + lane * 4);
      ffma2(az0, hv.x, W[c][0][0].x); ffma2(az0, hv.y, W[c][0][0].y);
      ffma2(ar0, hv.x, W[c][0][1].x); ffma2(ar0, hv.y, W[c][0][1].y);
      ffma2(an0, hv.x, W[c][0][2].x); ffma2(an0, hv.y, W[c][0][2].y);
      ffma2(az1, hv.x, W[c][1][0].x); ffma2(az1, hv.y, W[c][1][0].y);
      ffma2(ar1, hv.x, W[c][1][1].x); ffma2(ar1, hv.y, W[c][1][1].y);
      ffma2(an1, hv.x, W[c][1][2].x); ffma2(an1, hv.y, W[c][1][2].y);
    }
    {
      ulonglong2 hv = *(const ulonglong2 *)(hb + 384 + lane * 4);
      ulonglong2 wz0 = *(const ulonglong2 *)(p3_0);
      ulonglong2 wr0 = *(const ulonglong2 *)(p3_0 + 128);
      ulonglong2 wn0 = *(const ulonglong2 *)(p3_0 + 256);
      ulonglong2 wz1 = *(const ulonglong2 *)(p3_1);
      ulonglong2 wr1 = *(const ulonglong2 *)(p3_1 + 128);
      ulonglong2 wn1 = *(const ulonglong2 *)(p3_1 + 256);
      ffma2(az0, hv.x, wz0.x); ffma2(az0, hv.y, wz0.y);
      ffma2(ar0, hv.x, wr0.x); ffma2(ar0, hv.y, wr0.y);
      ffma2(an0, hv.x, wn0.x); ffma2(an0, hv.y, wn0.y);
      ffma2(az1, hv.x, wz1.x); ffma2(az1, hv.y, wz1.y);
      ffma2(ar1, hv.x, wr1.x); ffma2(ar1, hv.y, wr1.y);
      ffma2(an1, hv.x, wn1.x); ffma2(an1, hv.y, wn1.y);
    }
    float dz = pair_reduce(hsum2(az0), hsum2(az1), hi);
    float dr = pair_reduce(hsum2(ar0), hsum2(ar1), hi);
    float dn = pair_reduce(hsum2(an0), hsum2(an1), hi);

    float xt = sx0[t];
    float z  = sigf_fast(fmaf(xt, kz, cbz) + dz);
    float r  = sigf_fast(fmaf(xt, kr, cbr) + dr);
    float hh = tanhf_fast(fmaf(xt, kn, bin) + r * (dn + brn));
    float hold = hb[gu];
    float hnew = hh + z * (hold - hh);

    // Ensure tid0's expect_tx (and all reads of buffer p) precede any of this
    // CTA's stores -- our stores gate every other CTA's entry into step t+1.
    __syncthreads();

    if (t < WU - 1) {
      st_async_f32(ra[p ^ 1], rm[p ^ 1], hnew);
    } else {
      if ((lane & 15) == 0) lout[gu] = hnew;  // y0
    }
  }
}

// =====================================================================
// Chain kernel (96 CTAs persistent): 15 serial 2-step GRUs
// =====================================================================
__global__ void __launch_bounds__(NT, 1) chain_kernel(
    float *__restrict__ lout, const float *__restrict__ kc,
    const float *__restrict__ bc)
{
  __shared__ float sm_part[NW * 32];
  const int bid = blockIdx.x, tid = threadIdx.x;
  const int warp = tid >> 5, lane = tid & 31;
  unsigned gen = *(volatile unsigned *)&g_gen;

  for (int ci = 0; ci < 15; ++ci) {
    const float *yprev = lout + ci * WU;
    // pass1: gpart[half][col] = partial of y_prev . kc[ci][:,col]
    {
      int cb = bid >> 1, half = bid & 1;
      int col = cb * 32 + lane;
      const float *wp = kc + (size_t)ci * (WU * WCOLS) + col;
      float acc = 0.0f;
      for (int r0 = warp; r0 < 256; r0 += NW) {
        int r = half * 256 + r0;
        acc = fmaf(__ldcg(yprev + r), __ldg(wp + r * WCOLS), acc);
      }
      sm_part[warp * 32 + lane] = acc;
      __syncthreads();
      if (warp == 0) {
        float s = 0.0f;
#pragma unroll
        for (int w2 = 0; w2 < NW; ++w2) s += sm_part[w2 * 32 + lane];
        g_gpart[half * WCOLS + col] = s;
      }
    }
    grid_sync(gen, GC);
    // pass2: gates + y
    {
      int u = bid * NT + tid;
      if (u < WU) {
        float gxz = __ldcg(g_gpart + u) + __ldcg(g_gpart + WCOLS + u) +
                    __ldg(bc + ci * 3072 + u);
        float gxr = __ldcg(g_gpart + WU + u) + __ldcg(g_gpart + WCOLS + WU + u) +
                    __ldg(bc + ci * 3072 + WU + u);
        float gxh = __ldcg(g_gpart + 2 * WU + u) + __ldcg(g_gpart + WCOLS + 2 * WU + u) +
                    __ldg(bc + ci * 3072 + 2 * WU + u);
        float ghz = __ldcg(g_ghp + ci * WCOLS + u);
        float ghr = __ldcg(g_ghp + ci * WCOLS + WU + u);
        float ghn = __ldcg(g_ghp + ci * WCOLS + 2 * WU + u);
        float h1v = __ldcg(g_h1 + ci * WU + u);
        float z = sigmoidf_(gxz + ghz);
        float r = sigmoidf_(gxr + ghr);
        float hh = tanhf_(gxh + r * ghn);
        lout[(ci + 1) * WU + u] = z * h1v + (1.0f - z) * hh;
      }
    }
    grid_sync(gen, GC);
  }
}

// =====================================================================
// Host launcher
// =====================================================================
extern "C" void kernel_launch(void *const *d_in, const int *in_sizes, int n_in,
                              void *d_out, int out_size) {
  (void)in_sizes; (void)n_in; (void)out_size;
  const float *x = (const float *)d_in[0];
  const float *K0[3]  = {(const float *)d_in[1],  (const float *)d_in[7],  (const float *)d_in[13]};
  const float *RK0[3] = {(const float *)d_in[2],  (const float *)d_in[8],  (const float *)d_in[14]};
  const float *B0[3]  = {(const float *)d_in[3],  (const float *)d_in[9],  (const float *)d_in[15]};
  const float *KC[3]  = {(const float *)d_in[4],  (const float *)d_in[10], (const float *)d_in[16]};
  const float *RKC[3] = {(const float *)d_in[5],  (const float *)d_in[11], (const float *)d_in[17]};
  const float *BC[3]  = {(const float *)d_in[6],  (const float *)d_in[12], (const float *)d_in[18]};

  float *pA = nullptr, *pB = nullptr;
  cudaGetSymbolAddress((void **)&pA, g_bufA);
  cudaGetSymbolAddress((void **)&pB, g_bufB);

  cudaFuncSetAttribute(gru0_kernel, cudaFuncAttributeMaxDynamicSharedMemorySize, GRU0_SMEM);
  cudaFuncSetAttribute(gru0_kernel, cudaFuncAttributeNonPortableClusterSizeAllowed, 1);

  const float *LIN[3] = {x, pA, pB};
  float *LOUT[3] = {pA, pB, (float *)d_out};

  for (int l = 0; l < 3; ++l) {
    phases_kernel<<<GP, NT>>>(LIN[l], KC[l], RKC[l], BC[l]);

    cudaLaunchConfig_t cfg = {};
    cfg.gridDim = dim3(CL, 1, 1);
    cfg.blockDim = dim3(GT, 1, 1);
    cfg.dynamicSmemBytes = GRU0_SMEM;
    cfg.stream = 0;
    cudaLaunchAttribute attrs[1];
    attrs[0].id = cudaLaunchAttributeClusterDimension;
    attrs[0].val.clusterDim = {CL, 1, 1};
    cfg.attrs = attrs;
    cfg.numAttrs = 1;
    cudaLaunchKernelEx(&cfg, gru0_kernel, LIN[l], K0[l], RK0[l], B0[l], LOUT[l]);

    chain_kernel<<<GC, NT>>>(LOUT[l], KC[l], BC[l]);
  }
}

// round 7
// speedup vs baseline: 2.6748x; 1.3219x over previous
#include <cuda_runtime.h>
#include <cstdint>

#define NT 384
#define NW 12
#define WU 512
#define WCOLS 1536
#define GP 240   // phases grid (720 jobs x 4 row-quarters = 2880 warps)
#define GC 96    // chain grid
#define CL 16    // GRU0 cluster size
#define GT 256   // GRU0 threads per CTA (8 warps, 4 units/warp)

typedef unsigned long long u64;

// ---------------- device scratch (static, no allocation) ----------------
__device__ float g_bufA[16 * WU];
__device__ float g_bufB[16 * WU];
__device__ float g_h1[15 * WU];
__device__ float g_ghp[15 * WCOLS];
__device__ float g_gxc[15 * WCOLS];
__device__ float g_gpart[2 * WCOLS];
__device__ unsigned g_count;
__device__ unsigned g_gen;

// Grid-wide barrier among nct co-resident CTAs. Generation continues
// monotonically across kernel launches (wrap-safe signed compare).
__device__ __forceinline__ void grid_sync(unsigned &gen, unsigned nct) {
  unsigned next = gen + 1u;
  __threadfence();
  __syncthreads();
  if (threadIdx.x == 0) {
    if (atomicAdd(&g_count, 1u) == nct - 1u) {
      atomicExch(&g_count, 0u);
      __threadfence();
      atomicExch(&g_gen, next);
    } else {
      while ((int)(*(volatile unsigned *)&g_gen - next) < 0) { }
    }
  }
  gen = next;
  __syncthreads();
}

__device__ __forceinline__ float sigmoidf_(float x) {
  return 1.0f / (1.0f + __expf(-x));
}
__device__ __forceinline__ float tanhf_(float x) {
  float ax = fabsf(x);
  float e = __expf(-2.0f * ax);
  float t = (1.0f - e) / (1.0f + e);
  return copysignf(t, x);
}
__device__ __forceinline__ float sigf_fast(float x) {
  return __fdividef(1.0f, 1.0f + __expf(-x));
}
__device__ __forceinline__ float tanhf_fast(float x) {
  float ax = fabsf(x);
  float e = __expf(-2.0f * ax);
  float t = __fdividef(1.0f - e, 1.0f + e);
  return copysignf(t, x);
}

// ---------------- Blackwell helpers ----------------
__device__ __forceinline__ void ffma2(u64 &acc, u64 a, u64 b) {
  asm("fma.rn.f32x2 %0, %1, %2, %0;" : "+l"(acc) : "l"(a), "l"(b));
}
__device__ __forceinline__ float hsum2(u64 v) {
  float lo, hi;
  asm("mov.b64 {%0,%1}, %2;" : "=f"(lo), "=f"(hi) : "l"(v));
  return lo + hi;
}
__device__ __forceinline__ uint32_t mapa_u32(uint32_t laddr, unsigned rank) {
  uint32_t raddr;
  asm("mapa.shared::cluster.u32 %0, %1, %2;" : "=r"(raddr) : "r"(laddr), "r"(rank));
  return raddr;
}
__device__ __forceinline__ void st_async_f32(uint32_t raddr, uint32_t rmbar, float v) {
  asm volatile(
      "st.async.shared::cluster.mbarrier::complete_tx::bytes.b32 [%0], %1, [%2];"
      :: "r"(raddr), "r"(__float_as_uint(v)), "r"(rmbar) : "memory");
}
__device__ __forceinline__ void mbar_init(uint32_t mbar, unsigned cnt) {
  asm volatile("mbarrier.init.shared.b64 [%0], %1;" :: "r"(mbar), "r"(cnt) : "memory");
}
__device__ __forceinline__ void mbar_expect_tx(uint32_t mbar, unsigned bytes) {
  asm volatile("mbarrier.arrive.expect_tx.shared.b64 _, [%0], %1;"
               :: "r"(mbar), "r"(bytes) : "memory");
}
__device__ __forceinline__ void mbar_wait(uint32_t mbar, uint32_t parity) {
  uint32_t done;
  asm volatile(
      "{\n\t.reg .pred p;\n\t"
      "mbarrier.try_wait.parity.acquire.cta.shared::cta.b64 p, [%1], %2;\n\t"
      "selp.b32 %0, 1, 0, p;\n\t}"
      : "=r"(done) : "r"(mbar), "r"(parity) : "memory");
  if (!done) {
    asm volatile(
        "{\n\t.reg .pred P1;\n\t"
        "WAIT_LOOP_%=:\n\t"
        "mbarrier.try_wait.parity.acquire.cta.shared::cta.b64 P1, [%0], %1, 0x989680;\n\t"
        "@P1 bra.uni WAIT_DONE_%=;\n\t"
        "bra.uni WAIT_LOOP_%=;\n\t"
        "WAIT_DONE_%=:\n\t}"
        :: "r"(mbar), "r"(parity) : "memory");
  }
}
__device__ __forceinline__ void cluster_sync_() {
  asm volatile("barrier.cluster.arrive.aligned;" ::: "memory");
  asm volatile("barrier.cluster.wait.aligned;" ::: "memory");
}

// 4-unit paired warp reduction. Lane layout after reduce:
//   lanes 0-7 hold full sum of v0, 8-15 of v1, 16-23 of v2, 24-31 of v3.
__device__ __forceinline__ float quad_reduce(float v0, float v1, float v2,
                                             float v3, bool h16, bool h8) {
  float A  = h16 ? v2 : v0;
  float Ao = h16 ? v0 : v2;
  A += __shfl_xor_sync(0xffffffffu, Ao, 16);
  float B  = h16 ? v3 : v1;
  float Bo = h16 ? v1 : v3;
  B += __shfl_xor_sync(0xffffffffu, Bo, 16);
  float C  = h8 ? B : A;
  float Co = h8 ? A : B;
  C += __shfl_xor_sync(0xffffffffu, Co, 8);
  C += __shfl_xor_sync(0xffffffffu, C, 4);
  C += __shfl_xor_sync(0xffffffffu, C, 2);
  C += __shfl_xor_sync(0xffffffffu, C, 1);
  return C;
}

// =====================================================================
// Phases kernel (GP=240 CTAs, 2/SM): gxc -> h1 -> ghp for all 15 chain GRUs
// Each of the 720 column jobs split into 4 row-quarters (4 warps/job).
// =====================================================================
__global__ void __launch_bounds__(NT, 2) phases_kernel(
    const float *__restrict__ lin, const float *__restrict__ kc,
    const float *__restrict__ rkc, const float *__restrict__ bc)
{
  __shared__ float sm_x1[WU];
  __shared__ float sm_part[NW][32];
  const int bid = blockIdx.x, tid = threadIdx.x;
  const int warp = tid >> 5, lane = tid & 31;
  unsigned gen = *(volatile unsigned *)&g_gen;

  for (int i = tid; i < WU; i += NT) sm_x1[i] = __ldcg(lin + i * 16 + 1);
  __syncthreads();

  const int wg = bid * NW + warp;        // 0..2879
  const int job = wg >> 2, qtr = wg & 3; // 720 jobs x 4 quarters
  const int ci = job / 48;
  const int col = (job - ci * 48) * 32 + lane;

  // phase A: gxc[ci][col] = x1 . kc[ci][:,col] + b_i  (row-quarter split)
  {
    const float *wp = kc + (size_t)ci * (WU * WCOLS) + (size_t)(qtr * 128) * WCOLS + col;
    float a[16];
#pragma unroll
    for (int j = 0; j < 16; ++j) a[j] = 0.0f;
    for (int r = 0; r < 128; r += 16) {
#pragma unroll
      for (int j = 0; j < 16; ++j)
        a[j] = fmaf(sm_x1[qtr * 128 + r + j], __ldg(wp + (size_t)(r + j) * WCOLS), a[j]);
    }
    float s = 0.0f;
#pragma unroll
    for (int j = 0; j < 16; ++j) s += a[j];
    sm_part[warp][lane] = s;
    __syncthreads();
    if ((warp & 3) == 0) {
      float tot = sm_part[warp][lane] + sm_part[warp + 1][lane] +
                  sm_part[warp + 2][lane] + sm_part[warp + 3][lane];
      g_gxc[ci * WCOLS + col] = tot + __ldg(bc + ci * 3072 + col);
    }
  }
  grid_sync(gen, GP);

  // h1 pointwise (chain step 1, h=0)
  {
    int e = bid * NT + tid;
    if (e < 15 * WU) {
      int c2 = e >> 9, u = e & (WU - 1);
      float gz = __ldcg(g_gxc + c2 * WCOLS + u);
      float gr = __ldcg(g_gxc + c2 * WCOLS + WU + u);
      float gn = __ldcg(g_gxc + c2 * WCOLS + 2 * WU + u);
      float brz = __ldg(bc + c2 * 3072 + WCOLS + u);
      float brr = __ldg(bc + c2 * 3072 + WCOLS + WU + u);
      float brn = __ldg(bc + c2 * 3072 + WCOLS + 2 * WU + u);
      float z = sigmoidf_(gz + brz);
      float r = sigmoidf_(gr + brr);
      float hh = tanhf_(gn + r * brn);
      g_h1[e] = (1.0f - z) * hh;
    }
  }
  grid_sync(gen, GP);

  // phase B: ghp[ci][col] = h1[ci] . rkc[ci][:,col] + b_r  (row-quarter split)
  {
    const float *wp = rkc + (size_t)ci * (WU * WCOLS) + (size_t)(qtr * 128) * WCOLS + col;
    const float *hp = g_h1 + ci * WU + qtr * 128;
    float a[16];
#pragma unroll
    for (int j = 0; j < 16; ++j) a[j] = 0.0f;
    for (int r = 0; r < 128; r += 16) {
#pragma unroll
      for (int j = 0; j < 16; ++j)
        a[j] = fmaf(__ldcg(hp + r + j), __ldg(wp + (size_t)(r + j) * WCOLS), a[j]);
    }
    float s = 0.0f;
#pragma unroll
    for (int j = 0; j < 16; ++j) s += a[j];
    sm_part[warp][lane] = s;
    __syncthreads();
    if ((warp & 3) == 0) {
      float tot = sm_part[warp][lane] + sm_part[warp + 1][lane] +
                  sm_part[warp + 2][lane] + sm_part[warp + 3][lane];
      g_ghp[ci * WCOLS + col] = tot + __ldg(bc + ci * 3072 + WCOLS + col);
    }
  }
}

// =====================================================================
// GRU0 kernel: 16-CTA cluster, GT=256 (8 warps, 4 units/warp), ALL
// recurrent weights in registers (192 regs/thread). Per-step sync via
// st.async + tx-counted mbarrier; double-buffered h (WAR-safe: mbar[q]
// full => all threads finished step t => finished reading buffer p).
// =====================================================================
#define SWA_FLOATS (32 * 3 * WU)   // 49152 floats staging
#define GRU0_SMEM ((SWA_FLOATS + 2 * WU + WU + 4) * 4)

__global__ void __launch_bounds__(GT, 1) gru0_kernel(
    const float *__restrict__ lin, const float *__restrict__ k0,
    const float *__restrict__ rk0, const float *__restrict__ b0,
    float *__restrict__ lout)
{
  extern __shared__ float sm[];
  float *swA = sm;                        // [u][g][k] staging (dead after init)
  float *sh  = sm + SWA_FLOATS;           // [2][512] double-buffered h
  float *sx0 = sh + 2 * WU;               // [512]
  // mbar[2] after sx0

  unsigned rank;
  asm("mov.u32 %0, %%cluster_ctarank;" : "=r"(rank));
  const int tid = threadIdx.x, warp = tid >> 5, lane = tid & 31;
  const int base = (int)rank * 32;

  const uint32_t sm_u32 = (uint32_t)__cvta_generic_to_shared(sm);
  const uint32_t sh_u32 = sm_u32 + SWA_FLOATS * 4;
  const uint32_t mbar_u32 = sh_u32 + (2 * WU + WU) * 4;

  for (int i = tid; i < WU; i += GT) sx0[i] = __ldg(lin + 16 * i);
  for (int i = tid; i < 2 * WU; i += GT) sh[i] = 0.0f;
  // stage this CTA's 96 rec columns into SMEM, transposed to [u][g][k]
  for (int idx = tid; idx < 96 * WU; idx += GT) {
    int k = idx / 96, c2 = idx - k * 96;
    int g = c2 >> 5, u = c2 & 31;
    swA[(u * 3 + g) * WU + k] = __ldg(rk0 + (size_t)k * WCOLS + g * WU + base + u);
  }
  if (tid == 0) {
    mbar_init(mbar_u32, 1);
    mbar_init(mbar_u32 + 8, 1);
    mbar_expect_tx(mbar_u32, 2048);
    mbar_expect_tx(mbar_u32 + 8, 2048);
  }

  // lane group -> unit: myu = lane>>3 within this warp's 4 units
  const bool h16 = (lane & 16) != 0;
  const bool h8  = (lane & 8) != 0;
  const int myu = lane >> 3;
  const int gu = base + warp * 4 + myu;
  const float kz  = __ldg(k0 + gu);
  const float kr  = __ldg(k0 + WU + gu);
  const float kn  = __ldg(k0 + 2 * WU + gu);
  const float cbz = __ldg(b0 + gu) + __ldg(b0 + WCOLS + gu);
  const float cbr = __ldg(b0 + WU + gu) + __ldg(b0 + WCOLS + WU + gu);
  const float bin = __ldg(b0 + 2 * WU + gu);
  const float brn = __ldg(b0 + WCOLS + 2 * WU + gu);

  __syncthreads();

  // all weights into registers: W[c][u][g], k = c*128 + lane*4 .. +4
  ulonglong2 W[4][4][3];
#pragma unroll
  for (int c = 0; c < 4; ++c) {
#pragma unroll
    for (int uu = 0; uu < 4; ++uu) {
#pragma unroll
      for (int g = 0; g < 3; ++g) {
        W[c][uu][g] = *(const ulonglong2 *)(
            swA + ((warp * 4 + uu) * 3 + g) * WU + c * 128 + lane * 4);
      }
    }
  }

  // remote store targets: each lane feeds 2 ranks
  const unsigned tr0 = (unsigned)((lane & 7) * 2);
  const unsigned tr1 = tr0 + 1;
  uint32_t ra0[2], ra1[2], rm0[2], rm1[2];
#pragma unroll
  for (int b = 0; b < 2; ++b) {
    uint32_t loff = sh_u32 + ((unsigned)(b * WU + gu) << 2);
    uint32_t moff = mbar_u32 + 8 * b;
    ra0[b] = mapa_u32(loff, tr0);
    ra1[b] = mapa_u32(loff, tr1);
    rm0[b] = mapa_u32(moff, tr0);
    rm1[b] = mapa_u32(moff, tr1);
  }
  uint32_t ph0 = 0, ph1 = 0;

  cluster_sync_();  // all mbars initialized, all h buffers zeroed

  for (int t = 0; t < WU; ++t) {
    const int p = t & 1;
    if (t) {
      const uint32_t mb = mbar_u32 + 8 * p;
      if (p) { mbar_wait(mb, ph1); ph1 ^= 1; }
      else   { mbar_wait(mb, ph0); ph0 ^= 1; }
      if (tid == 0) mbar_expect_tx(mb, 2048);  // re-arm for next fill of p
    }
    const float *hb = sh + p * WU;
    ulonglong2 hv[4];
#pragma unroll
    for (int c = 0; c < 4; ++c)
      hv[c] = *(const ulonglong2 *)(hb + c * 128 + lane * 4);

    float s[4][3];
#pragma unroll
    for (int uu = 0; uu < 4; ++uu) {
      u64 az = 0, ar = 0, an = 0;
#pragma unroll
      for (int c = 0; c < 4; ++c) {
        ffma2(az, hv[c].x, W[c][uu][0].x); ffma2(az, hv[c].y, W[c][uu][0].y);
        ffma2(ar, hv[c].x, W[c][uu][1].x); ffma2(ar, hv[c].y, W[c][uu][1].y);
        ffma2(an, hv[c].x, W[c][uu][2].x); ffma2(an, hv[c].y, W[c][uu][2].y);
      }
      s[uu][0] = hsum2(az);
      s[uu][1] = hsum2(ar);
      s[uu][2] = hsum2(an);
    }
    float dz = quad_reduce(s[0][0], s[1][0], s[2][0], s[3][0], h16, h8);
    float dr = quad_reduce(s[0][1], s[1][1], s[2][1], s[3][1], h16, h8);
    float dn = quad_reduce(s[0][2], s[1][2], s[2][2], s[3][2], h16, h8);

    float xt = sx0[t];
    float z  = sigf_fast(fmaf(xt, kz, cbz) + dz);
    float r  = sigf_fast(fmaf(xt, kr, cbr) + dr);
    float hh = tanhf_fast(fmaf(xt, kn, bin) + r * (dn + brn));
    float hold = hb[gu];
    float hnew = hh + z * (hold - hh);

    // tid0's expect_tx (and all buffer-p reads) must precede our stores:
    // our stores gate every CTA's entry into step t+1.
    __syncthreads();

    if (t < WU - 1) {
      st_async_f32(ra0[p ^ 1], rm0[p ^ 1], hnew);
      st_async_f32(ra1[p ^ 1], rm1[p ^ 1], hnew);
    } else {
      if ((lane & 7) == 0) lout[gu] = hnew;  // y0
    }
  }
}

// =====================================================================
// Chain kernel (96 CTAs persistent): 15 serial 2-step GRUs
// =====================================================================
__global__ void __launch_bounds__(NT, 1) chain_kernel(
    float *__restrict__ lout, const float *__restrict__ kc,
    const float *__restrict__ bc)
{
  __shared__ float sm_part[NW * 32];
  const int bid = blockIdx.x, tid = threadIdx.x;
  const int warp = tid >> 5, lane = tid & 31;
  unsigned gen = *(volatile unsigned *)&g_gen;

  for (int ci = 0; ci < 15; ++ci) {
    const float *yprev = lout + ci * WU;
    // pass1: gpart[half][col] = partial of y_prev . kc[ci][:,col]
    {
      int cb = bid >> 1, half = bid & 1;
      int col = cb * 32 + lane;
      const float *wp = kc + (size_t)ci * (WU * WCOLS) + col;
      float acc = 0.0f;
      for (int r0 = warp; r0 < 256; r0 += NW) {
        int r = half * 256 + r0;
        acc = fmaf(__ldcg(yprev + r), __ldg(wp + r * WCOLS), acc);
      }
      sm_part[warp * 32 + lane] = acc;
      __syncthreads();
      if (warp == 0) {
        float s = 0.0f;
#pragma unroll
        for (int w2 = 0; w2 < NW; ++w2) s += sm_part[w2 * 32 + lane];
        g_gpart[half * WCOLS + col] = s;
      }
    }
    grid_sync(gen, GC);
    // pass2: gates + y
    {
      int u = bid * NT + tid;
      if (u < WU) {
        float gxz = __ldcg(g_gpart + u) + __ldcg(g_gpart + WCOLS + u) +
                    __ldg(bc + ci * 3072 + u);
        float gxr = __ldcg(g_gpart + WU + u) + __ldcg(g_gpart + WCOLS + WU + u) +
                    __ldg(bc + ci * 3072 + WU + u);
        float gxh = __ldcg(g_gpart + 2 * WU + u) + __ldcg(g_gpart + WCOLS + 2 * WU + u) +
                    __ldg(bc + ci * 3072 + 2 * WU + u);
        float ghz = __ldcg(g_ghp + ci * WCOLS + u);
        float ghr = __ldcg(g_ghp + ci * WCOLS + WU + u);
        float ghn = __ldcg(g_ghp + ci * WCOLS + 2 * WU + u);
        float h1v = __ldcg(g_h1 + ci * WU + u);
        float z = sigmoidf_(gxz + ghz);
        float r = sigmoidf_(gxr + ghr);
        float hh = tanhf_(gxh + r * ghn);
        lout[(ci + 1) * WU + u] = z * h1v + (1.0f - z) * hh;
      }
    }
    grid_sync(gen, GC);
  }
}

// =====================================================================
// Host launcher
// =====================================================================
extern "C" void kernel_launch(void *const *d_in, const int *in_sizes, int n_in,
                              void *d_out, int out_size) {
  (void)in_sizes; (void)n_in; (void)out_size;
  const float *x = (const float *)d_in[0];
  const float *K0[3]  = {(const float *)d_in[1],  (const float *)d_in[7],  (const float *)d_in[13]};
  const float *RK0[3] = {(const float *)d_in[2],  (const float *)d_in[8],  (const float *)d_in[14]};
  const float *B0[3]  = {(const float *)d_in[3],  (const float *)d_in[9],  (const float *)d_in[15]};
  const float *KC[3]  = {(const float *)d_in[4],  (const float *)d_in[10], (const float *)d_in[16]};
  const float *RKC[3] = {(const float *)d_in[5],  (const float *)d_in[11], (const float *)d_in[17]};
  const float *BC[3]  = {(const float *)d_in[6],  (const float *)d_in[12], (const float *)d_in[18]};

  float *pA = nullptr, *pB = nullptr;
  cudaGetSymbolAddress((void **)&pA, g_bufA);
  cudaGetSymbolAddress((void **)&pB, g_bufB);

  cudaFuncSetAttribute(gru0_kernel, cudaFuncAttributeMaxDynamicSharedMemorySize, GRU0_SMEM);
  cudaFuncSetAttribute(gru0_kernel, cudaFuncAttributeNonPortableClusterSizeAllowed, 1);

  const float *LIN[3] = {x, pA, pB};
  float *LOUT[3] = {pA, pB, (float *)d_out};

  for (int l = 0; l < 3; ++l) {
    phases_kernel<<<GP, NT>>>(LIN[l], KC[l], RKC[l], BC[l]);

    cudaLaunchConfig_t cfg = {};
    cfg.gridDim = dim3(CL, 1, 1);
    cfg.blockDim = dim3(GT, 1, 1);
    cfg.dynamicSmemBytes = GRU0_SMEM;
    cfg.stream = 0;
    cudaLaunchAttribute attrs[1];
    attrs[0].id = cudaLaunchAttributeClusterDimension;
    attrs[0].val.clusterDim = {CL, 1, 1};
    cfg.attrs = attrs;
    cfg.numAttrs = 1;
    cudaLaunchKernelEx(&cfg, gru0_kernel, LIN[l], K0[l], RK0[l], B0[l], LOUT[l]);

    chain_kernel<<<GC, NT>>>(LOUT[l], KC[l], BC[l]);
  }
}

// round 8
// speedup vs baseline: 2.7981x; 1.0461x over previous
#include <cuda_runtime.h>
#include <cstdint>

#define NT 384
#define NW 12
#define WU 512
#define WCOLS 1536
#define GP 240   // phases grid (720 jobs x 4 row-quarters = 2880 warps)
#define GC 96    // chain grid
#define CL 16    // GRU0 cluster size
#define GT 256   // GRU0 threads per CTA (8 warps, 4 units/warp)

typedef unsigned long long u64;

// ---------------- device scratch (static, no allocation) ----------------
__device__ float g_bufA[16 * WU];
__device__ float g_bufB[16 * WU];
__device__ float g_h1[15 * WU];
__device__ float g_ghp[15 * WCOLS];
__device__ float g_gxc[15 * WCOLS];
__device__ float g_gpart[4 * WCOLS];   // [ci&1][half][col]
__device__ unsigned g_count;
__device__ unsigned g_gen;

// Grid-wide barrier among nct co-resident CTAs. Generation continues
// monotonically across kernel launches (wrap-safe signed compare).
__device__ __forceinline__ void grid_sync(unsigned &gen, unsigned nct) {
  unsigned next = gen + 1u;
  __threadfence();
  __syncthreads();
  if (threadIdx.x == 0) {
    if (atomicAdd(&g_count, 1u) == nct - 1u) {
      atomicExch(&g_count, 0u);
      __threadfence();
      atomicExch(&g_gen, next);
    } else {
      while ((int)(*(volatile unsigned *)&g_gen - next) < 0) { }
    }
  }
  gen = next;
  __syncthreads();
}

__device__ __forceinline__ float sigmoidf_(float x) {
  return 1.0f / (1.0f + __expf(-x));
}
__device__ __forceinline__ float tanhf_(float x) {
  float ax = fabsf(x);
  float e = __expf(-2.0f * ax);
  float t = (1.0f - e) / (1.0f + e);
  return copysignf(t, x);
}
__device__ __forceinline__ float sigf_fast(float x) {
  return __fdividef(1.0f, 1.0f + __expf(-x));
}
__device__ __forceinline__ float tanhf_fast(float x) {
  float ax = fabsf(x);
  float e = __expf(-2.0f * ax);
  float t = __fdividef(1.0f - e, 1.0f + e);
  return copysignf(t, x);
}

// ---------------- Blackwell helpers ----------------
__device__ __forceinline__ void ffma2(u64 &acc, u64 a, u64 b) {
  asm("fma.rn.f32x2 %0, %1, %2, %0;" : "+l"(acc) : "l"(a), "l"(b));
}
__device__ __forceinline__ float hsum2(u64 v) {
  float lo, hi;
  asm("mov.b64 {%0,%1}, %2;" : "=f"(lo), "=f"(hi) : "l"(v));
  return lo + hi;
}
__device__ __forceinline__ uint32_t mapa_u32(uint32_t laddr, unsigned rank) {
  uint32_t raddr;
  asm("mapa.shared::cluster.u32 %0, %1, %2;" : "=r"(raddr) : "r"(laddr), "r"(rank));
  return raddr;
}
__device__ __forceinline__ void st_async_b64(uint32_t raddr, uint32_t rmbar, u64 v) {
  asm volatile(
      "st.async.shared::cluster.mbarrier::complete_tx::bytes.b64 [%0], %1, [%2];"
      :: "r"(raddr), "l"(v), "r"(rmbar) : "memory");
}
__device__ __forceinline__ void mbar_init(uint32_t mbar, unsigned cnt) {
  asm volatile("mbarrier.init.shared.b64 [%0], %1;" :: "r"(mbar), "r"(cnt) : "memory");
}
__device__ __forceinline__ void mbar_expect_tx(uint32_t mbar, unsigned bytes) {
  asm volatile("mbarrier.arrive.expect_tx.shared.b64 _, [%0], %1;"
               :: "r"(mbar), "r"(bytes) : "memory");
}
__device__ __forceinline__ void mbar_wait(uint32_t mbar, uint32_t parity) {
  uint32_t done;
  asm volatile(
      "{\n\t.reg .pred p;\n\t"
      "mbarrier.try_wait.parity.acquire.cta.shared::cta.b64 p, [%1], %2;\n\t"
      "selp.b32 %0, 1, 0, p;\n\t}"
      : "=r"(done) : "r"(mbar), "r"(parity) : "memory");
  if (!done) {
    asm volatile(
        "{\n\t.reg .pred P1;\n\t"
        "WAIT_LOOP_%=:\n\t"
        "mbarrier.try_wait.parity.acquire.cta.shared::cta.b64 P1, [%0], %1, 0x989680;\n\t"
        "@P1 bra.uni WAIT_DONE_%=;\n\t"
        "bra.uni WAIT_LOOP_%=;\n\t"
        "WAIT_DONE_%=:\n\t}"
        :: "r"(mbar), "r"(parity) : "memory");
  }
}
__device__ __forceinline__ void cluster_sync_() {
  asm volatile("barrier.cluster.arrive.aligned;" ::: "memory");
  asm volatile("barrier.cluster.wait.aligned;" ::: "memory");
}

// 4-unit paired warp reduction. Lane layout after reduce:
//   lanes 0-7 hold full sum of v0, 8-15 of v1, 16-23 of v2, 24-31 of v3.
__device__ __forceinline__ float quad_reduce(float v0, float v1, float v2,
                                             float v3, bool h16, bool h8) {
  float A  = h16 ? v2 : v0;
  float Ao = h16 ? v0 : v2;
  A += __shfl_xor_sync(0xffffffffu, Ao, 16);
  float B  = h16 ? v3 : v1;
  float Bo = h16 ? v1 : v3;
  B += __shfl_xor_sync(0xffffffffu, Bo, 16);
  float C  = h8 ? B : A;
  float Co = h8 ? A : B;
  C += __shfl_xor_sync(0xffffffffu, Co, 8);
  C += __shfl_xor_sync(0xffffffffu, C, 4);
  C += __shfl_xor_sync(0xffffffffu, C, 2);
  C += __shfl_xor_sync(0xffffffffu, C, 1);
  return C;
}

// =====================================================================
// Phases kernel (GP=240 CTAs, 2/SM): gxc -> h1 -> ghp for all 15 chain GRUs
// Each of the 720 column jobs split into 4 row-quarters (4 warps/job).
// =====================================================================
__global__ void __launch_bounds__(NT, 2) phases_kernel(
    const float *__restrict__ lin, const float *__restrict__ kc,
    const float *__restrict__ rkc, const float *__restrict__ bc)
{
  __shared__ float sm_x1[WU];
  __shared__ float sm_part[NW][32];
  const int bid = blockIdx.x, tid = threadIdx.x;
  const int warp = tid >> 5, lane = tid & 31;
  unsigned gen = *(volatile unsigned *)&g_gen;

  for (int i = tid; i < WU; i += NT) sm_x1[i] = __ldcg(lin + i * 16 + 1);
  __syncthreads();

  const int wg = bid * NW + warp;        // 0..2879
  const int job = wg >> 2, qtr = wg & 3; // 720 jobs x 4 quarters
  const int ci = job / 48;
  const int col = (job - ci * 48) * 32 + lane;

  // phase A: gxc[ci][col] = x1 . kc[ci][:,col] + b_i  (row-quarter split)
  {
    const float *wp = kc + (size_t)ci * (WU * WCOLS) + (size_t)(qtr * 128) * WCOLS + col;
    float a[16];
#pragma unroll
    for (int j = 0; j < 16; ++j) a[j] = 0.0f;
    for (int r = 0; r < 128; r += 16) {
#pragma unroll
      for (int j = 0; j < 16; ++j)
        a[j] = fmaf(sm_x1[qtr * 128 + r + j], __ldg(wp + (size_t)(r + j) * WCOLS), a[j]);
    }
    float s = 0.0f;
#pragma unroll
    for (int j = 0; j < 16; ++j) s += a[j];
    sm_part[warp][lane] = s;
    __syncthreads();
    if ((warp & 3) == 0) {
      float tot = sm_part[warp][lane] + sm_part[warp + 1][lane] +
                  sm_part[warp + 2][lane] + sm_part[warp + 3][lane];
      g_gxc[ci * WCOLS + col] = tot + __ldg(bc + ci * 3072 + col);
    }
  }
  grid_sync(gen, GP);

  // h1 pointwise (chain step 1, h=0)
  {
    int e = bid * NT + tid;
    if (e < 15 * WU) {
      int c2 = e >> 9, u = e & (WU - 1);
      float gz = __ldcg(g_gxc + c2 * WCOLS + u);
      float gr = __ldcg(g_gxc + c2 * WCOLS + WU + u);
      float gn = __ldcg(g_gxc + c2 * WCOLS + 2 * WU + u);
      float brz = __ldg(bc + c2 * 3072 + WCOLS + u);
      float brr = __ldg(bc + c2 * 3072 + WCOLS + WU + u);
      float brn = __ldg(bc + c2 * 3072 + WCOLS + 2 * WU + u);
      float z = sigmoidf_(gz + brz);
      float r = sigmoidf_(gr + brr);
      float hh = tanhf_(gn + r * brn);
      g_h1[e] = (1.0f - z) * hh;
    }
  }
  grid_sync(gen, GP);

  // phase B: ghp[ci][col] = h1[ci] . rkc[ci][:,col] + b_r  (row-quarter split)
  {
    const float *wp = rkc + (size_t)ci * (WU * WCOLS) + (size_t)(qtr * 128) * WCOLS + col;
    const float *hp = g_h1 + ci * WU + qtr * 128;
    float a[16];
#pragma unroll
    for (int j = 0; j < 16; ++j) a[j] = 0.0f;
    for (int r = 0; r < 128; r += 16) {
#pragma unroll
      for (int j = 0; j < 16; ++j)
        a[j] = fmaf(__ldcg(hp + r + j), __ldg(wp + (size_t)(r + j) * WCOLS), a[j]);
    }
    float s = 0.0f;
#pragma unroll
    for (int j = 0; j < 16; ++j) s += a[j];
    sm_part[warp][lane] = s;
    __syncthreads();
    if ((warp & 3) == 0) {
      float tot = sm_part[warp][lane] + sm_part[warp + 1][lane] +
                  sm_part[warp + 2][lane] + sm_part[warp + 3][lane];
      g_ghp[ci * WCOLS + col] = tot + __ldg(bc + ci * 3072 + WCOLS + col);
    }
  }
}

// =====================================================================
// GRU0 kernel: 16-CTA cluster, GT=256 (8 warps, 4 units/warp), ALL
// recurrent weights in registers. Per-step sync via b64-packed st.async
// (2 adjacent units per message -> 256 arrivals/mbar/step instead of 512)
// + tx-counted mbarrier; double-buffered h (WAR-safe).
// =====================================================================
#define SWA_FLOATS (32 * 3 * WU)   // 49152 floats staging
#define GRU0_SMEM ((SWA_FLOATS + 2 * WU + WU + 4) * 4)

__global__ void __launch_bounds__(GT, 1) gru0_kernel(
    const float *__restrict__ lin, const float *__restrict__ k0,
    const float *__restrict__ rk0, const float *__restrict__ b0,
    float *__restrict__ lout)
{
  extern __shared__ float sm[];
  float *swA = sm;                        // [u][g][k] staging (dead after init)
  float *sh  = sm + SWA_FLOATS;           // [2][512] double-buffered h
  float *sx0 = sh + 2 * WU;               // [512]
  // mbar[2] after sx0

  unsigned rank;
  asm("mov.u32 %0, %%cluster_ctarank;" : "=r"(rank));
  const int tid = threadIdx.x, warp = tid >> 5, lane = tid & 31;
  const int base = (int)rank * 32;

  const uint32_t sm_u32 = (uint32_t)__cvta_generic_to_shared(sm);
  const uint32_t sh_u32 = sm_u32 + SWA_FLOATS * 4;
  const uint32_t mbar_u32 = sh_u32 + (2 * WU + WU) * 4;

  for (int i = tid; i < WU; i += GT) sx0[i] = __ldg(lin + 16 * i);
  for (int i = tid; i < 2 * WU; i += GT) sh[i] = 0.0f;
  // stage this CTA's 96 rec columns into SMEM, transposed to [u][g][k]
  for (int idx = tid; idx < 96 * WU; idx += GT) {
    int k = idx / 96, c2 = idx - k * 96;
    int g = c2 >> 5, u = c2 & 31;
    swA[(u * 3 + g) * WU + k] = __ldg(rk0 + (size_t)k * WCOLS + g * WU + base + u);
  }
  if (tid == 0) {
    mbar_init(mbar_u32, 1);
    mbar_init(mbar_u32 + 8, 1);
    mbar_expect_tx(mbar_u32, 2048);
    mbar_expect_tx(mbar_u32 + 8, 2048);
  }

  // lane group -> unit: myu = lane>>3 within this warp's 4 units
  const bool h16 = (lane & 16) != 0;
  const bool h8  = (lane & 8) != 0;
  const int myu = lane >> 3;
  const int gu = base + warp * 4 + myu;
  const float kz  = __ldg(k0 + gu);
  const float kr  = __ldg(k0 + WU + gu);
  const float kn  = __ldg(k0 + 2 * WU + gu);
  const float cbz = __ldg(b0 + gu) + __ldg(b0 + WCOLS + gu);
  const float cbr = __ldg(b0 + WU + gu) + __ldg(b0 + WCOLS + WU + gu);
  const float bin = __ldg(b0 + 2 * WU + gu);
  const float brn = __ldg(b0 + WCOLS + 2 * WU + gu);

  __syncthreads();

  // all weights into registers: W[c][u][g], k = c*128 + lane*4 .. +4
  ulonglong2 W[4][4][3];
#pragma unroll
  for (int c = 0; c < 4; ++c) {
#pragma unroll
    for (int uu = 0; uu < 4; ++uu) {
#pragma unroll
      for (int g = 0; g < 3; ++g) {
        W[c][uu][g] = *(const ulonglong2 *)(
            swA + ((warp * 4 + uu) * 3 + g) * WU + c * 128 + lane * 4);
      }
    }
  }

  // b64 pair store targets: sender lanes 0-7 (units u0,u1) and 16-23 (u2,u3).
  // Each sender lane feeds 2 ranks. Pair base unit is even -> 8B aligned.
  const bool sender = (lane & 8) == 0;
  const int gu_pair = base + warp * 4 + (h16 ? 2 : 0);
  const unsigned tr0 = (unsigned)((lane & 7) * 2);
  const unsigned tr1 = tr0 + 1;
  uint32_t ra0[2], ra1[2], rm0[2], rm1[2];
#pragma unroll
  for (int b = 0; b < 2; ++b) {
    uint32_t loff = sh_u32 + ((unsigned)(b * WU + gu_pair) << 2);
    uint32_t moff = mbar_u32 + 8 * b;
    ra0[b] = mapa_u32(loff, tr0);
    ra1[b] = mapa_u32(loff, tr1);
    rm0[b] = mapa_u32(moff, tr0);
    rm1[b] = mapa_u32(moff, tr1);
  }
  uint32_t ph0 = 0, ph1 = 0;

  cluster_sync_();  // all mbars initialized, all h buffers zeroed

  for (int t = 0; t < WU; ++t) {
    const int p = t & 1;
    if (t) {
      const uint32_t mb = mbar_u32 + 8 * p;
      if (p) { mbar_wait(mb, ph1); ph1 ^= 1; }
      else   { mbar_wait(mb, ph0); ph0 ^= 1; }
      if (tid == 0) mbar_expect_tx(mb, 2048);  // re-arm for next fill of p
    }
    const float *hb = sh + p * WU;
    ulonglong2 hv[4];
#pragma unroll
    for (int c = 0; c < 4; ++c)
      hv[c] = *(const ulonglong2 *)(hb + c * 128 + lane * 4);

    float s[4][3];
#pragma unroll
    for (int uu = 0; uu < 4; ++uu) {
      u64 az = 0, ar = 0, an = 0;
#pragma unroll
      for (int c = 0; c < 4; ++c) {
        ffma2(az, hv[c].x, W[c][uu][0].x); ffma2(az, hv[c].y, W[c][uu][0].y);
        ffma2(ar, hv[c].x, W[c][uu][1].x); ffma2(ar, hv[c].y, W[c][uu][1].y);
        ffma2(an, hv[c].x, W[c][uu][2].x); ffma2(an, hv[c].y, W[c][uu][2].y);
      }
      s[uu][0] = hsum2(az);
      s[uu][1] = hsum2(ar);
      s[uu][2] = hsum2(an);
    }
    float dz = quad_reduce(s[0][0], s[1][0], s[2][0], s[3][0], h16, h8);
    float dr = quad_reduce(s[0][1], s[1][1], s[2][1], s[3][1], h16, h8);
    float dn = quad_reduce(s[0][2], s[1][2], s[2][2], s[3][2], h16, h8);

    float xt = sx0[t];
    float z  = sigf_fast(fmaf(xt, kz, cbz) + dz);
    float r  = sigf_fast(fmaf(xt, kr, cbr) + dr);
    float hh = tanhf_fast(fmaf(xt, kn, bin) + r * (dn + brn));
    float hold = hb[gu];
    float hnew = hh + z * (hold - hh);

    // pair-pack: lanes 0-7 get (u0,u1), lanes 16-23 get (u2,u3)
    float oth = __shfl_xor_sync(0xffffffffu, hnew, 8);
    u64 pk = (u64)__float_as_uint(hnew) | ((u64)__float_as_uint(oth) << 32);

    // tid0's expect_tx (and all buffer-p reads) must precede our stores:
    // our stores gate every CTA's entry into step t+1.
    __syncthreads();

    if (t < WU - 1) {
      if (sender) {
        st_async_b64(ra0[p ^ 1], rm0[p ^ 1], pk);
        st_async_b64(ra1[p ^ 1], rm1[p ^ 1], pk);
      }
    } else {
      if ((lane & 7) == 0) lout[gu] = hnew;  // y0
    }
  }
}

// =====================================================================
// Chain kernel (96 CTAs persistent): 15 serial 2-step GRUs.
// ONE grid_sync per step: after gpart, every CTA redundantly computes the
// full y(ci+1) into its own SMEM (pass1 reads y locally). g_gpart is
// double-buffered by ci-parity so pass1(ci+1) never races y-reads(ci).
// =====================================================================
__global__ void __launch_bounds__(NT, 1) chain_kernel(
    float *__restrict__ lout, const float *__restrict__ kc,
    const float *__restrict__ bc)
{
  __shared__ float sy[WU];
  __shared__ float sm_part[NW * 32];
  const int bid = blockIdx.x, tid = threadIdx.x;
  const int warp = tid >> 5, lane = tid & 31;
  unsigned gen = *(volatile unsigned *)&g_gen;

  for (int i = tid; i < WU; i += NT) sy[i] = __ldcg(lout + i);  // y0
  __syncthreads();

  const int cb = bid >> 1, half = bid & 1;
  const int col = cb * 32 + lane;

  for (int ci = 0; ci < 15; ++ci) {
    const int buf = ci & 1;
    float *gp = g_gpart + buf * 2 * WCOLS;
    // pass1: gp[half][col] = partial of y_prev . kc[ci][:,col]
    {
      const float *wp = kc + (size_t)ci * (WU * WCOLS) + col;
      float acc = 0.0f;
      for (int r0 = warp; r0 < 256; r0 += NW) {
        int r = half * 256 + r0;
        acc = fmaf(sy[r], __ldg(wp + r * WCOLS), acc);
      }
      sm_part[warp * 32 + lane] = acc;
      __syncthreads();
      if (warp == 0) {
        float s = 0.0f;
#pragma unroll
        for (int w2 = 0; w2 < NW; ++w2) s += sm_part[w2 * 32 + lane];
        gp[half * WCOLS + col] = s;
      }
    }
    grid_sync(gen, GC);
    // y-compute (all CTAs, redundant, into local sy)
    for (int u = tid; u < WU; u += NT) {
      float gxz = __ldcg(gp + u) + __ldcg(gp + WCOLS + u) +
                  __ldg(bc + ci * 3072 + u);
      float gxr = __ldcg(gp + WU + u) + __ldcg(gp + WCOLS + WU + u) +
                  __ldg(bc + ci * 3072 + WU + u);
      float gxh = __ldcg(gp + 2 * WU + u) + __ldcg(gp + WCOLS + 2 * WU + u) +
                  __ldg(bc + ci * 3072 + 2 * WU + u);
      float ghz = __ldcg(g_ghp + ci * WCOLS + u);
      float ghr = __ldcg(g_ghp + ci * WCOLS + WU + u);
      float ghn = __ldcg(g_ghp + ci * WCOLS + 2 * WU + u);
      float h1v = __ldcg(g_h1 + ci * WU + u);
      float z = sigmoidf_(gxz + ghz);
      float r = sigmoidf_(gxr + ghr);
      float hh = tanhf_(gxh + r * ghn);
      float y = z * h1v + (1.0f - z) * hh;
      sy[u] = y;
      if (bid == 0) lout[(ci + 1) * WU + u] = y;
    }
    __syncthreads();  // sy ready for next pass1 (CTA-local)
  }
}

// =====================================================================
// Host launcher
// =====================================================================
extern "C" void kernel_launch(void *const *d_in, const int *in_sizes, int n_in,
                              void *d_out, int out_size) {
  (void)in_sizes; (void)n_in; (void)out_size;
  const float *x = (const float *)d_in[0];
  const float *K0[3]  = {(const float *)d_in[1],  (const float *)d_in[7],  (const float *)d_in[13]};
  const float *RK0[3] = {(const float *)d_in[2],  (const float *)d_in[8],  (const float *)d_in[14]};
  const float *B0[3]  = {(const float *)d_in[3],  (const float *)d_in[9],  (const float *)d_in[15]};
  const float *KC[3]  = {(const float *)d_in[4],  (const float *)d_in[10], (const float *)d_in[16]};
  const float *RKC[3] = {(const float *)d_in[5],  (const float *)d_in[11], (const float *)d_in[17]};
  const float *BC[3]  = {(const float *)d_in[6],  (const float *)d_in[12], (const float *)d_in[18]};

  float *pA = nullptr, *pB = nullptr;
  cudaGetSymbolAddress((void **)&pA, g_bufA);
  cudaGetSymbolAddress((void **)&pB, g_bufB);

  cudaFuncSetAttribute(gru0_kernel, cudaFuncAttributeMaxDynamicSharedMemorySize, GRU0_SMEM);
  cudaFuncSetAttribute(gru0_kernel, cudaFuncAttributeNonPortableClusterSizeAllowed, 1);

  const float *LIN[3] = {x, pA, pB};
  float *LOUT[3] = {pA, pB, (float *)d_out};

  for (int l = 0; l < 3; ++l) {
    phases_kernel<<<GP, NT>>>(LIN[l], KC[l], RKC[l], BC[l]);

    cudaLaunchConfig_t cfg = {};
    cfg.gridDim = dim3(CL, 1, 1);
    cfg.blockDim = dim3(GT, 1, 1);
    cfg.dynamicSmemBytes = GRU0_SMEM;
    cfg.stream = 0;
    cudaLaunchAttribute attrs[1];
    attrs[0].id = cudaLaunchAttributeClusterDimension;
    attrs[0].val.clusterDim = {CL, 1, 1};
    cfg.attrs = attrs;
    cfg.numAttrs = 1;
    cudaLaunchKernelEx(&cfg, gru0_kernel, LIN[l], K0[l], RK0[l], B0[l], LOUT[l]);

    chain_kernel<<<GC, NT>>>(LOUT[l], KC[l], BC[l]);
  }
}